// round 9
// baseline (speedup 1.0000x reference)
#include <cuda_runtime.h>
#include <cstdint>

#define NGRID 16384
#define NH    8192
#define MODES 2049
#define BB    16
#define CIN   64
#define COUT  64
#define TDIM  256

#define ROW   546              // padded row stride (cplx) for the 16 k1-rows
#define USIZE (16 * ROW)       // 8736 cplx
#define TSIZE 512              // twiddle table entries (W_8192^t, t<512)

typedef unsigned long long cplx;   // packed float2 (re in lo, im in hi)

// ---------------- scratch (static device globals; no allocation) -------------
__device__ float2 g_xft[(size_t)BB * MODES * CIN];   // (B, M, Cin)
__device__ float2 g_oft[(size_t)BB * COUT * MODES];  // (B, Cout, M)
__device__ float2 g_tmod[(size_t)BB * MODES];        // (B, M)
__device__ float2 g_twid[TSIZE];                     // W_8192^t
__device__ float  g_xT [(size_t)BB * CIN  * NGRID];  // x transposed (B, C, N)
__device__ float  g_outT[(size_t)BB * COUT * NGRID]; // out transposed (B, C, N)

// ---------------- packed complex helpers -------------------------------------
__device__ __forceinline__ cplx pk(float x, float y) {
    cplx u; asm("mov.b64 %0, {%1, %2};" : "=l"(u) : "f"(x), "f"(y)); return u;
}
__device__ __forceinline__ void up(cplx u, float& x, float& y) {
    asm("mov.b64 {%0, %1}, %2;" : "=f"(x), "=f"(y) : "l"(u));
}
__device__ __forceinline__ cplx cadd2(cplx a, cplx b) {
    cplx r; asm("add.rn.f32x2 %0, %1, %2;" : "=l"(r) : "l"(a), "l"(b)); return r;
}
__device__ __forceinline__ cplx cfma2(cplx a, cplx b, cplx c) {
    cplx r; asm("fma.rn.f32x2 %0, %1, %2, %3;" : "=l"(r) : "l"(a), "l"(b), "l"(c)); return r;
}
// a - b  (exact: fma(b, -1, a))
__device__ __forceinline__ cplx csub2(cplx a, cplx b, cplx n1) { return cfma2(b, n1, a); }

// scalar complex mul of packed value by (wr, wi)
__device__ __forceinline__ cplx cmulc(cplx a, float wr, float wi) {
    float x, y; up(a, x, y);
    return pk(x * wr - y * wi, x * wi + y * wr);
}
__device__ __forceinline__ cplx cmulpf(cplx a, float2 w) { return cmulc(a, w.x, w.y); }

// float2 scalar complex helpers (for twiddle factor construction / untangle)
__device__ __forceinline__ float2 cmulf(float2 a, float2 b) {
    return make_float2(a.x * b.x - a.y * b.y, a.x * b.y + a.y * b.x);
}
__device__ __forceinline__ float2 caddf(float2 a, float2 b) { return make_float2(a.x + b.x, a.y + b.y); }
__device__ __forceinline__ float2 csubf(float2 a, float2 b) { return make_float2(a.x - b.x, a.y - b.y); }

// ---------------- packed register DFT-4 / DFT-16 ------------------------------
__device__ __forceinline__ void dft4p(cplx& a, cplx& b, cplx& c, cplx& d, cplx n1) {
    cplx t0 = cadd2(a, c), t1 = csub2(a, c, n1);
    cplx t2 = cadd2(b, d), t3 = csub2(b, d, n1);
    float x, y; up(t3, x, y);
    cplx t3i = pk(y, -x);               // -i * t3
    a = cadd2(t0, t2);
    c = csub2(t0, t2, n1);
    b = cadd2(t1, t3i);                 // t1 - i t3
    d = csub2(t1, t3i, n1);             // t1 + i t3
}

// In: v[j] natural order. Out: X[k1 + 4*k2] stored in slot (4*k1 + k2).
#define SLOT(k) ((((k) & 3) << 2) | ((k) >> 2))
__device__ __forceinline__ void dft16p(cplx v[16], cplx n1) {
    const float C1 = 0.9238795325112867f, S1 = 0.3826834323650898f, R = 0.7071067811865476f;
#pragma unroll
    for (int j = 0; j < 4; ++j)
        dft4p(v[j], v[4 + j], v[8 + j], v[12 + j], n1);
    v[5]  = cmulc(v[5],  C1, -S1);
    v[6]  = cmulc(v[6],  R,  -R );
    v[7]  = cmulc(v[7],  S1, -C1);
    v[9]  = cmulc(v[9],  R,  -R );
    { float x, y; up(v[10], x, y); v[10] = pk(y, -x); }   // * -i
    v[11] = cmulc(v[11], -R, -R );
    v[13] = cmulc(v[13], S1, -C1);
    v[14] = cmulc(v[14], -R, -R );
    v[15] = cmulc(v[15], -C1, S1);
#pragma unroll
    for (int k = 0; k < 4; ++k)
        dft4p(v[4 * k], v[4 * k + 1], v[4 * k + 2], v[4 * k + 3], n1);
}

// apply W^k (k = 1..15) as product of held powers {w1,w2,w3} x {w4,w8,w12}
__device__ __forceinline__ cplx twpow(cplx t, int k, float2 w1, float2 w2, float2 w3,
                                      float2 w4, float2 w8, float2 w12) {
    const int q = k >> 2, r = k & 3;
    if (q == 1) t = cmulpf(t, w4);
    else if (q == 2) t = cmulpf(t, w8);
    else if (q == 3) t = cmulpf(t, w12);
    if (r == 1) t = cmulpf(t, w1);
    else if (r == 2) t = cmulpf(t, w2);
    else if (r == 3) t = cmulpf(t, w3);
    return t;
}

// ---------------- shared 8192-pt forward-DFT core ----------------------------
// On entry: v[a] = z[512*a + m] (natural), m = tid. Tf[t] = W_8192^t, t<512.
// On exit:  v[SLOT(p)] = X[k1 + 16*q1 + 256*h + 512*p] for this thread's
//           (k1 = tid>>5, q1 = (tid>>1)&15, h = tid&1).
// If store_back: also stores X[k] to U[k + (k>>4)] and syncs.
__device__ __forceinline__ void fft8192_core(cplx v[16], cplx* U,
                                             const float2* Tf, int tid,
                                             bool store_back, cplx n1) {
    // W_32^u (stage-3 twiddles), compile-time constants
    const float2 W32[16] = {
        { 1.00000000000000f,  0.00000000000000f},
        { 0.98078528040323f, -0.19509032201613f},
        { 0.92387953251129f, -0.38268343236509f},
        { 0.83146961230255f, -0.55557023301960f},
        { 0.70710678118655f, -0.70710678118655f},
        { 0.55557023301960f, -0.83146961230255f},
        { 0.38268343236509f, -0.92387953251129f},
        { 0.19509032201613f, -0.98078528040323f},
        { 0.00000000000000f, -1.00000000000000f},
        {-0.19509032201613f, -0.98078528040323f},
        {-0.38268343236509f, -0.92387953251129f},
        {-0.55557023301960f, -0.83146961230255f},
        {-0.70710678118655f, -0.70710678118655f},
        {-0.83146961230255f, -0.55557023301960f},
        {-0.92387953251129f, -0.38268343236509f},
        {-0.98078528040323f, -0.19509032201613f}};
    const int m = tid;
    // ---- stage 1: DFT16 over a, twiddle W^{m*k}, store rows U[k*ROW + m]
    dft16p(v, n1);
    {
        float2 w1 = Tf[m];
        float2 w2 = cmulf(w1, w1), w3 = cmulf(w2, w1);
        float2 w4 = cmulf(w2, w2), w8 = cmulf(w4, w4), w12 = cmulf(w8, w4);
        U[m] = v[0];                    // SLOT(0) == 0
#pragma unroll
        for (int k = 1; k < 16; ++k)
            U[k * ROW + m] = twpow(v[SLOT(k)], k, w1, w2, w3, w4, w8, w12);
    }
    __syncthreads();
    // ---- stage 2: per (k1,u): DFT16 over b, twiddle W_512^{u*q1} = W_8192^{16u*q1}
    {
        const int k1 = tid >> 5, u = tid & 31;
        cplx* Urow = U + k1 * ROW;
#pragma unroll
        for (int b = 0; b < 16; ++b) v[b] = Urow[32 * b + u];
        dft16p(v, n1);
        float2 w1 = Tf[16 * u];
        float2 w2 = cmulf(w1, w1), w3 = cmulf(w2, w1);
        float2 w4 = cmulf(w2, w2), w8 = cmulf(w4, w4), w12 = cmulf(w8, w4);
        Urow[u] = v[0];
#pragma unroll
        for (int q1 = 1; q1 < 16; ++q1)
            Urow[34 * q1 + u] = twpow(v[SLOT(q1)], q1, w1, w2, w3, w4, w8, w12);
    }
    __syncthreads();
    // ---- stage 3: per (k1,q1,h): radix-2 combine + DFT16 over u'
    {
        const int k1 = tid >> 5, q1 = (tid >> 1) & 15, h = tid & 1;
        const cplx* Urow = U + k1 * ROW + 34 * q1;
#pragma unroll
        for (int up_ = 0; up_ < 16; ++up_) {
            cplx ca = Urow[up_];
            cplx cb = Urow[up_ + 16];
            if (h == 0) v[up_] = cadd2(ca, cb);
            else        v[up_] = cmulpf(csub2(ca, cb, n1), W32[up_]);
        }
        __syncthreads();                 // everyone done reading U
        dft16p(v, n1);
        if (store_back) {
            const int kb = k1 + 16 * q1 + 256 * h;
#pragma unroll
            for (int p = 0; p < 16; ++p) {
                int k = kb + 512 * p;
                U[k + (k >> 4)] = v[SLOT(p)];
            }
            __syncthreads();
        }
    }
}

__device__ __forceinline__ void load_table(float2* Tf, int tid) {
    if (tid < TSIZE) Tf[tid] = g_twid[tid];
}

// ---------------- kernel 0: twiddle table init -------------------------------
__global__ void twid_kernel() {
    int t = blockIdx.x * blockDim.x + threadIdx.x;
    if (t >= TSIZE) return;
    float s, c;
    sincospif((float)t * (-1.0f / 4096.0f), &s, &c);   // W_8192^t
    g_twid[t] = make_float2(c, s);
}

// ---------------- kernel 1: t_mod = t_emb @ dense^T (complex) ----------------
__global__ void tmod_kernel(const float* __restrict__ te,
                            const float* __restrict__ dr,
                            const float* __restrict__ di) {
    int idx = blockIdx.x * blockDim.x + threadIdx.x;
    if (idx >= BB * MODES) return;
    int b = idx & (BB - 1);
    int i = idx >> 4;
    const float* t  = te + b * TDIM;
    const float* rr = dr + (size_t)i * TDIM;
    const float* ri = di + (size_t)i * TDIM;
    float ar = 0.f, ai = 0.f;
#pragma unroll 8
    for (int k = 0; k < TDIM; ++k) {
        float tv = t[k];
        ar += tv * rr[k];
        ai += tv * ri[k];
    }
    g_tmod[(size_t)b * MODES + i] = make_float2(ar, ai);
}

// ---------------- transpose kernels ------------------------------------------
// x (B, N, C) -> g_xT (B, C, N).  Tile 64(n) x 64(c), fully coalesced.
__global__ __launch_bounds__(256) void transpose_in_kernel(const float* __restrict__ src) {
    __shared__ float tile[64][65];
    const int tx = threadIdx.x & 63, ty = threadIdx.x >> 6;
    const int b = blockIdx.y;
    const size_t n0 = (size_t)blockIdx.x * 64;
    const float* s = src + ((size_t)b * NGRID + n0) * CIN;
#pragma unroll
    for (int i = 0; i < 16; ++i) {
        int r = ty + 4 * i;
        tile[r][tx] = s[(size_t)r * CIN + tx];
    }
    __syncthreads();
    float* d = g_xT + (size_t)b * CIN * NGRID + n0;
#pragma unroll
    for (int i = 0; i < 16; ++i) {
        int c = ty + 4 * i;
        d[(size_t)c * NGRID + tx] = tile[tx][c];
    }
}

// g_outT (B, C, N) -> out (B, N, C).
__global__ __launch_bounds__(256) void transpose_out_kernel(float* __restrict__ dst) {
    __shared__ float tile[64][65];
    const int tx = threadIdx.x & 63, ty = threadIdx.x >> 6;
    const int b = blockIdx.y;
    const size_t n0 = (size_t)blockIdx.x * 64;
    const float* s = g_outT + (size_t)b * COUT * NGRID + n0;
#pragma unroll
    for (int i = 0; i < 16; ++i) {
        int c = ty + 4 * i;
        tile[c][tx] = s[(size_t)c * NGRID + tx];
    }
    __syncthreads();
    float* d = dst + ((size_t)b * NGRID + n0) * COUT;
#pragma unroll
    for (int i = 0; i < 16; ++i) {
        int r = ty + 4 * i;
        d[(size_t)r * COUT + tx] = tile[tx][r];
    }
}

// ---------------- kernel 2: forward rfft per (b, cin) ------------------------
__global__ __launch_bounds__(512, 2) void fwd_fft_kernel() {
    extern __shared__ cplx shp[];
    cplx*   U  = shp;
    float2* Tf = (float2*)(shp + USIZE);
    const int tid = threadIdx.x;
    const int b = blockIdx.x >> 6;
    const int c = blockIdx.x & 63;
    const cplx* xb = (const cplx*)(g_xT + ((size_t)b * CIN + c) * NGRID);
    const cplx n1 = pk(-1.f, -1.f);

    // load z[512a + m] = x[2m'] + i x[2m'+1], coalesced 64-bit
    cplx v[16];
#pragma unroll
    for (int a = 0; a < 16; ++a) v[a] = xb[512 * a + tid];
    load_table(Tf, tid);
    __syncthreads();

    fft8192_core(v, U, Tf, tid, true, n1);

    // real-FFT untangle, forward norm (1/N)
    const float invN = 1.0f / 16384.0f;
    const float2 EJ[5] = {
        {1.f, 0.f},
        {0.98078528040323f, -0.19509032201613f},
        {0.92387953251129f, -0.38268343236509f},
        {0.83146961230255f, -0.55557023301960f},
        {0.70710678118655f, -0.70710678118655f}};
    float sm, cm;
    sincospif((float)tid * (-1.0f / 8192.0f), &sm, &cm);  // e^{-i*pi*tid/8192}
    float2 wm = make_float2(cm, sm);
#pragma unroll
    for (int j = 0; j < 5; ++j) {
        int k = tid + 512 * j;
        if (k > 2048) break;
        int km = (NH - k) & (NH - 1);
        float zx, zy, cx, cy;
        up(U[k + (k >> 4)], zx, zy);
        up(U[km + (km >> 4)], cx, cy);
        float2 Zk  = make_float2(zx, zy);
        float2 Zcc = make_float2(cx, -cy);
        float2 E = make_float2(0.5f * (Zk.x + Zcc.x), 0.5f * (Zk.y + Zcc.y));
        float2 Od = csubf(Zk, Zcc);
        float2 O = make_float2(0.5f * Od.y, -0.5f * Od.x);  // -i/2 * Od
        float2 w = cmulf(wm, EJ[j]);                         // e^{-2pi i k/16384}
        float2 X = caddf(E, cmulf(w, O));
        g_xft[((size_t)b * MODES + k) * CIN + c] = make_float2(X.x * invN, X.y * invN);
    }
}

// ---------------- kernel 3: per-mode complex matmul + modulation -------------
__global__ __launch_bounds__(256) void specmul_kernel(const float* __restrict__ wr,
                                                      const float* __restrict__ wi) {
    __shared__ float  sWr[CIN * COUT];
    __shared__ float  sWi[CIN * COUT];
    __shared__ float2 sx[BB * CIN];
    __shared__ float2 stm[BB];
    const int i   = blockIdx.x;
    const int tid = threadIdx.x;

    const float4* wrb = (const float4*)(wr + (size_t)i * CIN * COUT);
    const float4* wib = (const float4*)(wi + (size_t)i * CIN * COUT);
#pragma unroll
    for (int t = 0; t < 4; ++t) {
        ((float4*)sWr)[tid + 256 * t] = wrb[tid + 256 * t];
        ((float4*)sWi)[tid + 256 * t] = wib[tid + 256 * t];
    }
    for (int t = tid; t < BB * CIN; t += 256) {
        int b = t >> 6, c = t & 63;
        sx[t] = g_xft[((size_t)b * MODES + i) * CIN + c];
    }
    if (tid < BB) stm[tid] = g_tmod[(size_t)tid * MODES + i];
    __syncthreads();

    const int o  = tid & 63;
    const int b0 = tid >> 6;     // 0..3
    float2 acc[4];
#pragma unroll
    for (int bb = 0; bb < 4; ++bb) acc[bb] = make_float2(0.f, 0.f);

#pragma unroll 4
    for (int c = 0; c < CIN; ++c) {
        float Wr = sWr[c * COUT + o];
        float Wi = sWi[c * COUT + o];
#pragma unroll
        for (int bb = 0; bb < 4; ++bb) {
            float2 xv = sx[(bb * 4 + b0) * CIN + c];
            acc[bb].x += xv.x * Wr - xv.y * Wi;
            acc[bb].y += xv.x * Wi + xv.y * Wr;
        }
    }
#pragma unroll
    for (int bb = 0; bb < 4; ++bb) {
        int b = bb * 4 + b0;
        float2 r = cmulf(stm[b], acc[bb]);
        g_oft[((size_t)b * COUT + o) * MODES + i] = r;
    }
}

// ---------------- kernel 4: zero-padded irfft per (b, cout) ------------------
__global__ __launch_bounds__(512, 2) void inv_fft_kernel() {
    extern __shared__ cplx shp[];
    cplx*   U  = shp;
    float2* Tf = (float2*)(shp + USIZE);
    const int tid = threadIdx.x;
    const int b = blockIdx.x >> 6;
    const int o = blockIdx.x & 63;
    const float2* of = g_oft + ((size_t)b * COUT + o) * MODES;
    const cplx n1 = pk(-1.f, -1.f);

    load_table(Tf, tid);

    // Build conj(Z)[512a + m] in registers (m = tid), folding the half-complex
    // untangle: Z[k] = A + i * (e^{+2pi i k/16384} * (OF - OC)),
    // A = OF + OC, OF = out_ft[k] (k<=2048, Im(OF[0])=0), OC = conj(out_ft[N-k]).
    const float2 EA[16] = {
        { 1.00000000000000f, 0.00000000000000f},
        { 0.98078528040323f, 0.19509032201613f},
        { 0.92387953251129f, 0.38268343236509f},
        { 0.83146961230255f, 0.55557023301960f},
        { 0.70710678118655f, 0.70710678118655f},
        { 0.55557023301960f, 0.83146961230255f},
        { 0.38268343236509f, 0.92387953251129f},
        { 0.19509032201613f, 0.98078528040323f},
        { 0.00000000000000f, 1.00000000000000f},
        {-0.19509032201613f, 0.98078528040323f},
        {-0.38268343236509f, 0.92387953251129f},
        {-0.55557023301960f, 0.83146961230255f},
        {-0.70710678118655f, 0.70710678118655f},
        {-0.83146961230255f, 0.55557023301960f},
        {-0.92387953251129f, 0.38268343236509f},
        {-0.98078528040323f, 0.19509032201613f}};
    float sm, cm;
    sincospif((float)tid * (1.0f / 8192.0f), &sm, &cm);    // e^{+i*pi*tid/8192}
    float2 wm = make_float2(cm, sm);

    cplx v[16];
#pragma unroll
    for (int a = 0; a < 16; ++a) {
        int k = 512 * a + tid;
        float2 OF = make_float2(0.f, 0.f);
        float2 OC = make_float2(0.f, 0.f);
        if (k < MODES) OF = of[k];
        if (k == 0) OF.y = 0.f;                 // irfft drops Im of bin 0
        if (k >= NH - 2048) {                   // N-k <= 2048 (k>0)
            float2 t = of[NH - k];
            OC = make_float2(t.x, -t.y);
        }
        float2 A  = caddf(OF, OC);
        float2 Bd = csubf(OF, OC);
        float2 w  = cmulf(wm, EA[a]);           // e^{+2pi i k/16384}
        float2 Bt = cmulf(w, Bd);
        v[a] = pk(A.x - Bt.y, -(A.y + Bt.x));   // conj(Z[k])
    }
    __syncthreads();

    fft8192_core(v, U, Tf, tid, true, n1);     // F[n] now in U (skewed, natural)

    // coalesced store: out[2n], out[2n+1] are contiguous in outT row
    float2* ob = (float2*)(g_outT + ((size_t)b * COUT + o) * NGRID);
#pragma unroll
    for (int j = 0; j < 16; ++j) {
        int n = tid + 512 * j;
        float fx, fy;
        up(U[n + (n >> 4)], fx, fy);
        ob[n] = make_float2(fx, -fy);
    }
}

// ---------------- launch ------------------------------------------------------
extern "C" void kernel_launch(void* const* d_in, const int* in_sizes, int n_in,
                              void* d_out, int out_size) {
    const float* x   = (const float*)d_in[0];
    const float* te  = (const float*)d_in[1];
    const float* wr  = (const float*)d_in[2];
    const float* wi  = (const float*)d_in[3];
    const float* drw = (const float*)d_in[4];
    const float* diw = (const float*)d_in[5];
    float* out = (float*)d_out;

    const int smem = USIZE * (int)sizeof(cplx) + TSIZE * (int)sizeof(float2);  // 73984 B
    cudaFuncSetAttribute(fwd_fft_kernel, cudaFuncAttributeMaxDynamicSharedMemorySize, smem);
    cudaFuncSetAttribute(inv_fft_kernel, cudaFuncAttributeMaxDynamicSharedMemorySize, smem);

    twid_kernel<<<1, TSIZE>>>();
    {
        int total = BB * MODES;
        int threads = 256;
        int blocks = (total + threads - 1) / threads;
        tmod_kernel<<<blocks, threads>>>(te, drw, diw);
    }
    transpose_in_kernel<<<dim3(NGRID / 64, BB), 256>>>(x);
    fwd_fft_kernel<<<BB * CIN, 512, smem>>>();
    specmul_kernel<<<MODES, 256>>>(wr, wi);
    inv_fft_kernel<<<BB * COUT, 512, smem>>>();
    transpose_out_kernel<<<dim3(NGRID / 64, BB), 256>>>(out);
}

// round 12
// speedup vs baseline: 1.4242x; 1.4242x over previous
#include <cuda_runtime.h>
#include <cstdint>

#define NGRID 16384
#define NH    8192
#define MODES 2049
#define BB    16
#define CIN   64
#define COUT  64
#define TDIM  256

#define ROW   546              // padded row stride (float2) for the 16 k1-rows
#define USIZE (16 * ROW)       // 8736 float2
#define TSIZE 4096             // twiddle table entries

// ---------------- scratch (static device globals; no allocation) -------------
__device__ float2 g_xft[(size_t)BB * MODES * CIN];   // (B, M, Cin)
__device__ float2 g_oft[(size_t)BB * COUT * MODES];  // (B, Cout, M)
__device__ float2 g_tmod[(size_t)BB * MODES];        // (B, M)
__device__ float2 g_twid[TSIZE];                     // W_8192^t
__device__ float  g_xT [(size_t)BB * CIN  * NGRID];  // x transposed (B, C, N)
__device__ float  g_outT[(size_t)BB * COUT * NGRID]; // out transposed (B, C, N)

// ---------------- complex helpers -------------------------------------------
__device__ __forceinline__ float2 cmul(float2 a, float2 b) {
    return make_float2(a.x * b.x - a.y * b.y, a.x * b.y + a.y * b.x);
}
__device__ __forceinline__ float2 cadd(float2 a, float2 b) { return make_float2(a.x + b.x, a.y + b.y); }
__device__ __forceinline__ float2 csub(float2 a, float2 b) { return make_float2(a.x - b.x, a.y - b.y); }

// ---------------- register DFT-4 / DFT-16 ------------------------------------
__device__ __forceinline__ void dft4(float2& a, float2& b, float2& c, float2& d) {
    float2 t0 = cadd(a, c), t1 = csub(a, c), t2 = cadd(b, d), t3 = csub(b, d);
    a = cadd(t0, t2);
    c = csub(t0, t2);
    b = cadd(t1, make_float2(t3.y, -t3.x));   // t1 - i*t3
    d = cadd(t1, make_float2(-t3.y, t3.x));   // t1 + i*t3
}

// In: v[j] natural order. Out: X[k1 + 4*k2] stored in slot (4*k1 + k2).
#define SLOT(k) ((((k) & 3) << 2) | ((k) >> 2))

__device__ __forceinline__ void dft16_twiddle_rows(float2 v[16]) {
    const float C1 = 0.9238795325112867f, S1 = 0.3826834323650898f, R = 0.7071067811865476f;
    v[5]  = cmul(v[5],  make_float2( C1, -S1));   // W16^1
    v[6]  = cmul(v[6],  make_float2( R,  -R ));   // W16^2
    v[7]  = cmul(v[7],  make_float2( S1, -C1));   // W16^3
    v[9]  = cmul(v[9],  make_float2( R,  -R ));   // W16^2
    v[10] = make_float2(v[10].y, -v[10].x);       // W16^4 = -i
    v[11] = cmul(v[11], make_float2(-R,  -R ));   // W16^6
    v[13] = cmul(v[13], make_float2( S1, -C1));   // W16^3
    v[14] = cmul(v[14], make_float2(-R,  -R ));   // W16^6
    v[15] = cmul(v[15], make_float2(-C1,  S1));   // W16^9
#pragma unroll
    for (int k1 = 0; k1 < 4; ++k1)
        dft4(v[4 * k1], v[4 * k1 + 1], v[4 * k1 + 2], v[4 * k1 + 3]);
}

__device__ __forceinline__ void dft16(float2 v[16]) {
#pragma unroll
    for (int j2 = 0; j2 < 4; ++j2)
        dft4(v[j2], v[4 + j2], v[8 + j2], v[12 + j2]);
    dft16_twiddle_rows(v);
}

// Sparse variant: v[4..11] are known zero. Column dft4 over (a, 0, 0, d):
// out = (a+d, a+i d, a-d, a-i d).
__device__ __forceinline__ void dft16_sparse(float2 v[16]) {
#pragma unroll
    for (int j = 0; j < 4; ++j) {
        float2 a = v[j], d = v[12 + j];
        float2 id = make_float2(-d.y, d.x);     // i*d
        v[j]      = cadd(a, d);
        v[4 + j]  = cadd(a, id);
        v[8 + j]  = csub(a, d);
        v[12 + j] = csub(a, id);
    }
    dft16_twiddle_rows(v);
}

// ---------------- shared 8192-pt forward-DFT core ----------------------------
// On entry: v holds stage-1 dft16 outputs for z[512*a + m], m = tid.
// T[t] = W_8192^t, t<4096.
__device__ __forceinline__ void fft8192_tail(float2 v[16], float2* U,
                                             const float2* T, int tid,
                                             bool store_back) {
    const int m = tid;
    // ---- stage 1 epilogue: twiddle W^{m*k}, store rows U[k*ROW + m]
    {
        float2 w = T[m];                 // W^m  (m < 512)
        float2 vw = make_float2(1.f, 0.f);
#pragma unroll
        for (int k = 0; k < 16; ++k) {
            U[k * ROW + m] = cmul(v[SLOT(k)], vw);
            vw = cmul(vw, w);
        }
    }
    __syncthreads();
    // ---- stage 2: per (k1,u): DFT16 over b, twiddle W_512^{u*q1}
    {
        const int k1 = tid >> 5, u = tid & 31;
        float2* Urow = U + k1 * ROW;
#pragma unroll
        for (int b = 0; b < 16; ++b) v[b] = Urow[32 * b + u];
        dft16(v);
        float2 w = T[16 * u];            // W_512^u
        float2 vw = make_float2(1.f, 0.f);
#pragma unroll
        for (int q1 = 0; q1 < 16; ++q1) {
            Urow[34 * q1 + u] = cmul(v[SLOT(q1)], vw);
            vw = cmul(vw, w);
        }
    }
    __syncthreads();
    // ---- stage 3: per (k1,q1,h): radix-2 combine + DFT16 over u'
    {
        const int k1 = tid >> 5, q1 = (tid >> 1) & 15, h = tid & 1;
        const float2* Urow = U + k1 * ROW + 34 * q1;
#pragma unroll
        for (int up = 0; up < 16; ++up) {
            float2 ca = Urow[up];
            float2 cb = Urow[up + 16];
            if (h == 0) v[up] = cadd(ca, cb);
            else        v[up] = cmul(csub(ca, cb), T[256 * up]);   // * W_32^{u'}
        }
        __syncthreads();                 // everyone done reading U
        dft16(v);
        if (store_back) {
            const int kb = k1 + 16 * q1 + 256 * h;
#pragma unroll
            for (int p = 0; p < 16; ++p) {
                int k = kb + 512 * p;
                U[k + (k >> 4)] = v[SLOT(p)];
            }
            __syncthreads();
        }
    }
}

__device__ __forceinline__ void load_table(float2* T, int tid) {
#pragma unroll
    for (int j = 0; j < TSIZE / 512; ++j) {
        int t = tid + 512 * j;
        T[t] = g_twid[t];
    }
}

// ---------------- kernel 0: twiddle table init -------------------------------
__global__ void twid_kernel() {
    int t = blockIdx.x * blockDim.x + threadIdx.x;
    if (t >= TSIZE) return;
    float s, c;
    sincospif((float)t * (-1.0f / 4096.0f), &s, &c);   // W_8192^t
    g_twid[t] = make_float2(c, s);
}

// ---------------- kernel 1: t_mod = t_emb @ dense^T (complex) ----------------
__global__ void tmod_kernel(const float* __restrict__ te,
                            const float* __restrict__ dr,
                            const float* __restrict__ di) {
    int idx = blockIdx.x * blockDim.x + threadIdx.x;
    if (idx >= BB * MODES) return;
    int b = idx & (BB - 1);
    int i = idx >> 4;
    const float* t  = te + b * TDIM;
    const float* rr = dr + (size_t)i * TDIM;
    const float* ri = di + (size_t)i * TDIM;
    float ar = 0.f, ai = 0.f;
#pragma unroll 8
    for (int k = 0; k < TDIM; ++k) {
        float tv = t[k];
        ar += tv * rr[k];
        ai += tv * ri[k];
    }
    g_tmod[(size_t)b * MODES + i] = make_float2(ar, ai);
}

// ---------------- transpose kernels ------------------------------------------
// x (B, N, C) -> g_xT (B, C, N).  Tile 64(n) x 64(c), fully coalesced.
__global__ __launch_bounds__(256) void transpose_in_kernel(const float* __restrict__ src) {
    __shared__ float tile[64][65];
    const int tx = threadIdx.x & 63, ty = threadIdx.x >> 6;
    const int b = blockIdx.y;
    const size_t n0 = (size_t)blockIdx.x * 64;
    const float* s = src + ((size_t)b * NGRID + n0) * CIN;
#pragma unroll
    for (int i = 0; i < 16; ++i) {
        int r = ty + 4 * i;
        tile[r][tx] = s[(size_t)r * CIN + tx];
    }
    __syncthreads();
    float* d = g_xT + (size_t)b * CIN * NGRID + n0;
#pragma unroll
    for (int i = 0; i < 16; ++i) {
        int c = ty + 4 * i;
        d[(size_t)c * NGRID + tx] = tile[tx][c];
    }
}

// g_outT (B, C, N) -> out (B, N, C).
__global__ __launch_bounds__(256) void transpose_out_kernel(float* __restrict__ dst) {
    __shared__ float tile[64][65];
    const int tx = threadIdx.x & 63, ty = threadIdx.x >> 6;
    const int b = blockIdx.y;
    const size_t n0 = (size_t)blockIdx.x * 64;
    const float* s = g_outT + (size_t)b * COUT * NGRID + n0;
#pragma unroll
    for (int i = 0; i < 16; ++i) {
        int c = ty + 4 * i;
        tile[c][tx] = s[(size_t)c * NGRID + tx];
    }
    __syncthreads();
    float* d = dst + ((size_t)b * NGRID + n0) * COUT;
#pragma unroll
    for (int i = 0; i < 16; ++i) {
        int r = ty + 4 * i;
        d[(size_t)r * COUT + tx] = tile[tx][r];
    }
}

// ---------------- kernel 2: forward rfft per (b, cin) ------------------------
__global__ __launch_bounds__(512, 2) void fwd_fft_kernel() {
    extern __shared__ float2 sh[];
    float2* U = sh;
    float2* T = sh + USIZE;
    const int tid = threadIdx.x;
    const int b = blockIdx.x >> 6;
    const int c = blockIdx.x & 63;
    const float2* xb = (const float2*)(g_xT + ((size_t)b * CIN + c) * NGRID);

    // load z[512a + m] = x[2m'] + i x[2m'+1], coalesced float2
    float2 v[16];
#pragma unroll
    for (int a = 0; a < 16; ++a) v[a] = xb[512 * a + tid];
    load_table(T, tid);
    __syncthreads();

    dft16(v);
    fft8192_tail(v, U, T, tid, true);

    // real-FFT untangle, forward norm (1/N)
    const float invN = 1.0f / 16384.0f;
    const float2 EJ[5] = {
        {1.f, 0.f},
        {0.98078528040323f, -0.19509032201613f},
        {0.92387953251129f, -0.38268343236509f},
        {0.83146961230255f, -0.55557023301960f},
        {0.70710678118655f, -0.70710678118655f}};
    float sm, cm;
    sincospif((float)tid * (-1.0f / 8192.0f), &sm, &cm);  // e^{-i*pi*tid/8192}
    float2 wm = make_float2(cm, sm);
#pragma unroll
    for (int j = 0; j < 5; ++j) {
        int k = tid + 512 * j;
        if (k > 2048) break;
        int km = (NH - k) & (NH - 1);
        float2 Zk = U[k + (k >> 4)];
        float2 Zc = U[km + (km >> 4)];
        float2 Zcc = make_float2(Zc.x, -Zc.y);
        float2 E = make_float2(0.5f * (Zk.x + Zcc.x), 0.5f * (Zk.y + Zcc.y));
        float2 Od = csub(Zk, Zcc);
        float2 O = make_float2(0.5f * Od.y, -0.5f * Od.x);  // -i/2 * Od
        float2 w = cmul(wm, EJ[j]);                          // e^{-2pi i k/16384}
        float2 X = cadd(E, cmul(w, O));
        g_xft[((size_t)b * MODES + k) * CIN + c] = make_float2(X.x * invN, X.y * invN);
    }
}

// ---------------- kernel 3: per-mode complex matmul + modulation -------------
__global__ __launch_bounds__(256) void specmul_kernel(const float* __restrict__ wr,
                                                      const float* __restrict__ wi) {
    __shared__ float2 sW[CIN * COUT];    // interleaved (Wr, Wi)
    __shared__ float2 sx[BB * CIN];
    __shared__ float2 stm[BB];
    const int i   = blockIdx.x;
    const int tid = threadIdx.x;

    const float4* wrb = (const float4*)(wr + (size_t)i * CIN * COUT);
    const float4* wib = (const float4*)(wi + (size_t)i * CIN * COUT);
#pragma unroll
    for (int t = 0; t < 4; ++t) {
        float4 r4 = wrb[tid + 256 * t];
        float4 i4 = wib[tid + 256 * t];
        int base = 4 * (tid + 256 * t);
        sW[base + 0] = make_float2(r4.x, i4.x);
        sW[base + 1] = make_float2(r4.y, i4.y);
        sW[base + 2] = make_float2(r4.z, i4.z);
        sW[base + 3] = make_float2(r4.w, i4.w);
    }
    for (int t = tid; t < BB * CIN; t += 256) {
        int b = t >> 6, c = t & 63;
        sx[t] = g_xft[((size_t)b * MODES + i) * CIN + c];
    }
    if (tid < BB) stm[tid] = g_tmod[(size_t)tid * MODES + i];
    __syncthreads();

    const int o  = tid & 63;
    const int b0 = tid >> 6;     // 0..3
    float2 acc[4];
#pragma unroll
    for (int bb = 0; bb < 4; ++bb) acc[bb] = make_float2(0.f, 0.f);

#pragma unroll 4
    for (int c = 0; c < CIN; ++c) {
        float2 Wv = sW[c * COUT + o];
#pragma unroll
        for (int bb = 0; bb < 4; ++bb) {
            float2 xv = sx[(bb * 4 + b0) * CIN + c];
            acc[bb].x += xv.x * Wv.x - xv.y * Wv.y;
            acc[bb].y += xv.x * Wv.y + xv.y * Wv.x;
        }
    }
#pragma unroll
    for (int bb = 0; bb < 4; ++bb) {
        int b = bb * 4 + b0;
        float2 r = cmul(stm[b], acc[bb]);
        g_oft[((size_t)b * COUT + o) * MODES + i] = r;
    }
}

// ---------------- kernel 4: zero-padded irfft per (b, cout) ------------------
__global__ __launch_bounds__(512, 2) void inv_fft_kernel() {
    extern __shared__ float2 sh[];
    float2* U = sh;
    float2* T = sh + USIZE;
    const int tid = threadIdx.x;
    const int b = blockIdx.x >> 6;
    const int o = blockIdx.x & 63;
    const float2* of = g_oft + ((size_t)b * COUT + o) * MODES;

    load_table(T, tid);

    // Build conj(Z)[512a + m] in registers (m = tid), folding the half-complex
    // untangle. Nonzero only for a in {0..3, 12..15} (and a=4 when tid==0).
    const float2 EA[16] = {
        { 1.00000000000000f, 0.00000000000000f},
        { 0.98078528040323f, 0.19509032201613f},
        { 0.92387953251129f, 0.38268343236509f},
        { 0.83146961230255f, 0.55557023301960f},
        { 0.70710678118655f, 0.70710678118655f},
        { 0.55557023301960f, 0.83146961230255f},
        { 0.38268343236509f, 0.92387953251129f},
        { 0.19509032201613f, 0.98078528040323f},
        { 0.00000000000000f, 1.00000000000000f},
        {-0.19509032201613f, 0.98078528040323f},
        {-0.38268343236509f, 0.92387953251129f},
        {-0.55557023301960f, 0.83146961230255f},
        {-0.70710678118655f, 0.70710678118655f},
        {-0.83146961230255f, 0.55557023301960f},
        {-0.92387953251129f, 0.38268343236509f},
        {-0.98078528040323f, 0.19509032201613f}};
    float sm, cm;
    sincospif((float)tid * (1.0f / 8192.0f), &sm, &cm);    // e^{+i*pi*tid/8192}
    float2 wm = make_float2(cm, sm);

    float2 v[16];
#pragma unroll
    for (int a = 0; a < 16; ++a) {
        if (a >= 5 && a <= 11) { v[a] = make_float2(0.f, 0.f); continue; }
        int k = 512 * a + tid;
        float2 OF = make_float2(0.f, 0.f);
        float2 OC = make_float2(0.f, 0.f);
        if (k < MODES) OF = of[k];
        if (k == 0) OF.y = 0.f;                 // irfft drops Im of bin 0
        if (k >= NH - 2048) {                   // N-k <= 2048 (k>0)
            float2 t = of[NH - k];
            OC = make_float2(t.x, -t.y);
        }
        float2 A  = cadd(OF, OC);
        float2 Bd = csub(OF, OC);
        float2 w  = cmul(wm, EA[a]);            // e^{+2pi i k/16384}
        float2 Bt = cmul(w, Bd);
        v[a] = make_float2(A.x - Bt.y, -(A.y + Bt.x));   // conj(Z[k])
    }
    __syncthreads();

    // stage-1 DFT16: sparse (v[4..11] == 0) for all threads except tid 0,
    // whose v[4] (mode k = 2048) is nonzero.
    if (tid == 0) dft16(v);
    else          dft16_sparse(v);
    fft8192_tail(v, U, T, tid, true);          // F[n] now in U (skewed, natural)

    // coalesced store: out[2n], out[2n+1] are contiguous in outT row
    float2* ob = (float2*)(g_outT + ((size_t)b * COUT + o) * NGRID);
#pragma unroll
    for (int j = 0; j < 16; ++j) {
        int n = tid + 512 * j;
        float2 F = U[n + (n >> 4)];
        ob[n] = make_float2(F.x, -F.y);
    }
}

// ---------------- launch ------------------------------------------------------
extern "C" void kernel_launch(void* const* d_in, const int* in_sizes, int n_in,
                              void* d_out, int out_size) {
    const float* x   = (const float*)d_in[0];
    const float* te  = (const float*)d_in[1];
    const float* wr  = (const float*)d_in[2];
    const float* wi  = (const float*)d_in[3];
    const float* drw = (const float*)d_in[4];
    const float* diw = (const float*)d_in[5];
    float* out = (float*)d_out;

    const int smem = (USIZE + TSIZE) * sizeof(float2);   // 102656 bytes
    cudaFuncSetAttribute(fwd_fft_kernel, cudaFuncAttributeMaxDynamicSharedMemorySize, smem);
    cudaFuncSetAttribute(inv_fft_kernel, cudaFuncAttributeMaxDynamicSharedMemorySize, smem);

    twid_kernel<<<TSIZE / 512, 512>>>();
    {
        int total = BB * MODES;
        int threads = 256;
        int blocks = (total + threads - 1) / threads;
        tmod_kernel<<<blocks, threads>>>(te, drw, diw);
    }
    transpose_in_kernel<<<dim3(NGRID / 64, BB), 256>>>(x);
    fwd_fft_kernel<<<BB * CIN, 512, smem>>>();
    specmul_kernel<<<MODES, 256>>>(wr, wi);
    inv_fft_kernel<<<BB * COUT, 512, smem>>>();
    transpose_out_kernel<<<dim3(NGRID / 64, BB), 256>>>(out);
}

// round 13
// speedup vs baseline: 1.5114x; 1.0612x over previous
#include <cuda_runtime.h>
#include <cstdint>

#define NGRID 16384
#define NH    8192
#define MODES 2049
#define BB    16
#define CIN   64
#define COUT  64
#define TDIM  256

#define ROW   546              // padded row stride (float2) for the 16 k1-rows
#define USIZE (16 * ROW)       // 8736 float2
#define TSIZE 4096             // twiddle table entries

// ---------------- scratch (static device globals; no allocation) -------------
__device__ float2 g_xft[(size_t)BB * MODES * CIN];   // (B, M, Cin)
__device__ float2 g_oft[(size_t)BB * COUT * MODES];  // (B, Cout, M)
__device__ float2 g_twid[TSIZE];                     // W_8192^t
__device__ float  g_xT [(size_t)BB * CIN  * NGRID];  // x transposed (B, C, N)
__device__ float  g_outT[(size_t)BB * COUT * NGRID]; // out transposed (B, C, N)

// ---------------- complex helpers -------------------------------------------
__device__ __forceinline__ float2 cmul(float2 a, float2 b) {
    return make_float2(a.x * b.x - a.y * b.y, a.x * b.y + a.y * b.x);
}
__device__ __forceinline__ float2 cadd(float2 a, float2 b) { return make_float2(a.x + b.x, a.y + b.y); }
__device__ __forceinline__ float2 csub(float2 a, float2 b) { return make_float2(a.x - b.x, a.y - b.y); }

// ---------------- register DFT-4 / DFT-16 ------------------------------------
__device__ __forceinline__ void dft4(float2& a, float2& b, float2& c, float2& d) {
    float2 t0 = cadd(a, c), t1 = csub(a, c), t2 = cadd(b, d), t3 = csub(b, d);
    a = cadd(t0, t2);
    c = csub(t0, t2);
    b = cadd(t1, make_float2(t3.y, -t3.x));   // t1 - i*t3
    d = cadd(t1, make_float2(-t3.y, t3.x));   // t1 + i*t3
}

// In: v[j] natural order. Out: X[k1 + 4*k2] stored in slot (4*k1 + k2).
#define SLOT(k) ((((k) & 3) << 2) | ((k) >> 2))

__device__ __forceinline__ void dft16_twiddle_rows(float2 v[16]) {
    const float C1 = 0.9238795325112867f, S1 = 0.3826834323650898f, R = 0.7071067811865476f;
    v[5]  = cmul(v[5],  make_float2( C1, -S1));   // W16^1
    v[6]  = cmul(v[6],  make_float2( R,  -R ));   // W16^2
    v[7]  = cmul(v[7],  make_float2( S1, -C1));   // W16^3
    v[9]  = cmul(v[9],  make_float2( R,  -R ));   // W16^2
    v[10] = make_float2(v[10].y, -v[10].x);       // W16^4 = -i
    v[11] = cmul(v[11], make_float2(-R,  -R ));   // W16^6
    v[13] = cmul(v[13], make_float2( S1, -C1));   // W16^3
    v[14] = cmul(v[14], make_float2(-R,  -R ));   // W16^6
    v[15] = cmul(v[15], make_float2(-C1,  S1));   // W16^9
#pragma unroll
    for (int k1 = 0; k1 < 4; ++k1)
        dft4(v[4 * k1], v[4 * k1 + 1], v[4 * k1 + 2], v[4 * k1 + 3]);
}

__device__ __forceinline__ void dft16(float2 v[16]) {
#pragma unroll
    for (int j2 = 0; j2 < 4; ++j2)
        dft4(v[j2], v[4 + j2], v[8 + j2], v[12 + j2]);
    dft16_twiddle_rows(v);
}

// Sparse variant: v[4..11] are known zero. Column dft4 over (a, 0, 0, d):
// out = (a+d, a+i d, a-d, a-i d).
__device__ __forceinline__ void dft16_sparse(float2 v[16]) {
#pragma unroll
    for (int j = 0; j < 4; ++j) {
        float2 a = v[j], d = v[12 + j];
        float2 id = make_float2(-d.y, d.x);     // i*d
        v[j]      = cadd(a, d);
        v[4 + j]  = cadd(a, id);
        v[8 + j]  = csub(a, d);
        v[12 + j] = csub(a, id);
    }
    dft16_twiddle_rows(v);
}

// ---------------- shared 8192-pt forward-DFT core ----------------------------
// On entry: v holds stage-1 dft16 outputs for z[512*a + m], m = tid.
// T[t] = W_8192^t, t<4096.
// prune_out: skip stores of X[k] with k>>9 in {5..11} (never read by fwd untangle).
__device__ __forceinline__ void fft8192_tail(float2 v[16], float2* U,
                                             const float2* T, int tid,
                                             bool store_back, bool prune_out) {
    const int m = tid;
    // ---- stage 1 epilogue: twiddle W^{m*k}, store rows U[k*ROW + m]
    {
        float2 w = T[m];                 // W^m  (m < 512)
        float2 vw = make_float2(1.f, 0.f);
#pragma unroll
        for (int k = 0; k < 16; ++k) {
            U[k * ROW + m] = cmul(v[SLOT(k)], vw);
            vw = cmul(vw, w);
        }
    }
    __syncthreads();
    // ---- stage 2: per (k1,u): DFT16 over b, twiddle W_512^{u*q1}
    {
        const int k1 = tid >> 5, u = tid & 31;
        float2* Urow = U + k1 * ROW;
#pragma unroll
        for (int b = 0; b < 16; ++b) v[b] = Urow[32 * b + u];
        dft16(v);
        float2 w = T[16 * u];            // W_512^u
        float2 vw = make_float2(1.f, 0.f);
#pragma unroll
        for (int q1 = 0; q1 < 16; ++q1) {
            Urow[34 * q1 + u] = cmul(v[SLOT(q1)], vw);
            vw = cmul(vw, w);
        }
    }
    __syncthreads();
    // ---- stage 3: per (k1,q1,h): radix-2 combine + DFT16 over u'
    {
        const int k1 = tid >> 5, q1 = (tid >> 1) & 15, h = tid & 1;
        const float2* Urow = U + k1 * ROW + 34 * q1;
#pragma unroll
        for (int up = 0; up < 16; ++up) {
            float2 ca = Urow[up];
            float2 cb = Urow[up + 16];
            if (h == 0) v[up] = cadd(ca, cb);
            else        v[up] = cmul(csub(ca, cb), T[256 * up]);   // * W_32^{u'}
        }
        __syncthreads();                 // everyone done reading U
        dft16(v);
        if (store_back) {
            const int kb = k1 + 16 * q1 + 256 * h;
#pragma unroll
            for (int p = 0; p < 16; ++p) {
                if (prune_out && p >= 5 && p <= 11) continue;
                int k = kb + 512 * p;
                U[k + (k >> 4)] = v[SLOT(p)];
            }
            __syncthreads();
        }
    }
}

__device__ __forceinline__ void load_table(float2* T, int tid) {
#pragma unroll
    for (int j = 0; j < TSIZE / 512; ++j) {
        int t = tid + 512 * j;
        T[t] = g_twid[t];
    }
}

// ---------------- transpose kernels ------------------------------------------
// x (B, N, C) -> g_xT (B, C, N).  Tile 64(n) x 64(c), fully coalesced.
// Blocks (x<8, y==0) additionally build the global twiddle table.
__global__ __launch_bounds__(256) void transpose_in_kernel(const float* __restrict__ src) {
    __shared__ float tile[64][65];
    const int tx = threadIdx.x & 63, ty = threadIdx.x >> 6;
    const int b = blockIdx.y;
    const size_t n0 = (size_t)blockIdx.x * 64;

    if (blockIdx.y == 0 && blockIdx.x < 8) {
#pragma unroll
        for (int j = 0; j < 2; ++j) {
            int t = blockIdx.x * 512 + threadIdx.x + 256 * j;
            float s, c;
            sincospif((float)t * (-1.0f / 4096.0f), &s, &c);   // W_8192^t
            g_twid[t] = make_float2(c, s);
        }
    }

    const float* s = src + ((size_t)b * NGRID + n0) * CIN;
#pragma unroll
    for (int i = 0; i < 16; ++i) {
        int r = ty + 4 * i;
        tile[r][tx] = s[(size_t)r * CIN + tx];
    }
    __syncthreads();
    float* d = g_xT + (size_t)b * CIN * NGRID + n0;
#pragma unroll
    for (int i = 0; i < 16; ++i) {
        int c = ty + 4 * i;
        d[(size_t)c * NGRID + tx] = tile[tx][c];
    }
}

// g_outT (B, C, N) -> out (B, N, C).
__global__ __launch_bounds__(256) void transpose_out_kernel(float* __restrict__ dst) {
    __shared__ float tile[64][65];
    const int tx = threadIdx.x & 63, ty = threadIdx.x >> 6;
    const int b = blockIdx.y;
    const size_t n0 = (size_t)blockIdx.x * 64;
    const float* s = g_outT + (size_t)b * COUT * NGRID + n0;
#pragma unroll
    for (int i = 0; i < 16; ++i) {
        int c = ty + 4 * i;
        tile[c][tx] = s[(size_t)c * NGRID + tx];
    }
    __syncthreads();
    float* d = dst + ((size_t)b * NGRID + n0) * COUT;
#pragma unroll
    for (int i = 0; i < 16; ++i) {
        int r = ty + 4 * i;
        d[(size_t)r * COUT + tx] = tile[tx][r];
    }
}

// ---------------- kernel 2: forward rfft per (b, cin) ------------------------
__global__ __launch_bounds__(512, 2) void fwd_fft_kernel() {
    extern __shared__ float2 sh[];
    float2* U = sh;
    float2* T = sh + USIZE;
    const int tid = threadIdx.x;
    const int b = blockIdx.x >> 6;
    const int c = blockIdx.x & 63;
    const float2* xb = (const float2*)(g_xT + ((size_t)b * CIN + c) * NGRID);

    // load z[512a + m] = x[2m'] + i x[2m'+1], coalesced float2
    float2 v[16];
#pragma unroll
    for (int a = 0; a < 16; ++a) v[a] = xb[512 * a + tid];
    load_table(T, tid);
    __syncthreads();

    dft16(v);
    fft8192_tail(v, U, T, tid, true, true);

    // real-FFT untangle, forward norm (1/N)
    const float invN = 1.0f / 16384.0f;
    const float2 EJ[5] = {
        {1.f, 0.f},
        {0.98078528040323f, -0.19509032201613f},
        {0.92387953251129f, -0.38268343236509f},
        {0.83146961230255f, -0.55557023301960f},
        {0.70710678118655f, -0.70710678118655f}};
    float sm, cm;
    sincospif((float)tid * (-1.0f / 8192.0f), &sm, &cm);  // e^{-i*pi*tid/8192}
    float2 wm = make_float2(cm, sm);
#pragma unroll
    for (int j = 0; j < 5; ++j) {
        int k = tid + 512 * j;
        if (k > 2048) break;
        int km = (NH - k) & (NH - 1);
        float2 Zk = U[k + (k >> 4)];
        float2 Zc = U[km + (km >> 4)];
        float2 Zcc = make_float2(Zc.x, -Zc.y);
        float2 E = make_float2(0.5f * (Zk.x + Zcc.x), 0.5f * (Zk.y + Zcc.y));
        float2 Od = csub(Zk, Zcc);
        float2 O = make_float2(0.5f * Od.y, -0.5f * Od.x);  // -i/2 * Od
        float2 w = cmul(wm, EJ[j]);                          // e^{-2pi i k/16384}
        float2 X = cadd(E, cmul(w, O));
        g_xft[((size_t)b * MODES + k) * CIN + c] = make_float2(X.x * invN, X.y * invN);
    }
}

// ---------------- kernel 3: per-mode complex matmul + modulation + tmod ------
// out_ft[b,i,o] = t_mod[b,i] * sum_c x_ft[b,i,c] * W[i,c,o], t_mod computed here.
__global__ __launch_bounds__(256) void specmul_kernel(const float* __restrict__ wr,
                                                      const float* __restrict__ wi,
                                                      const float* __restrict__ te,
                                                      const float* __restrict__ dr,
                                                      const float* __restrict__ di) {
    __shared__ float2 sW[CIN * COUT];    // interleaved (Wr, Wi)
    __shared__ float4 sx4[BB * CIN];     // (xr, xi, xr+xi, 0)
    __shared__ float2 stm[BB];
    const int i   = blockIdx.x;
    const int tid = threadIdx.x;

    const float4* wrb = (const float4*)(wr + (size_t)i * CIN * COUT);
    const float4* wib = (const float4*)(wi + (size_t)i * CIN * COUT);
#pragma unroll
    for (int t = 0; t < 4; ++t) {
        float4 r4 = wrb[tid + 256 * t];
        float4 i4 = wib[tid + 256 * t];
        int base = 4 * (tid + 256 * t);
        sW[base + 0] = make_float2(r4.x, i4.x);
        sW[base + 1] = make_float2(r4.y, i4.y);
        sW[base + 2] = make_float2(r4.z, i4.z);
        sW[base + 3] = make_float2(r4.w, i4.w);
    }
    for (int t = tid; t < BB * CIN; t += 256) {
        int b = t >> 6, c = t & 63;
        float2 xv = g_xft[((size_t)b * MODES + i) * CIN + c];
        sx4[t] = make_float4(xv.x, xv.y, xv.x + xv.y, 0.f);
    }

    // t_mod: warp w computes stm[w] and stm[w+8] via warp-reduced dot products
    {
        const int w = tid >> 5, lane = tid & 31;
        const float* dri = dr + (size_t)i * TDIM;
        const float* dii = di + (size_t)i * TDIM;
        const float* t1 = te + w * TDIM;
        const float* t2 = te + (w + 8) * TDIM;
        float a1 = 0.f, b1 = 0.f, a2 = 0.f, b2 = 0.f;
#pragma unroll
        for (int j = 0; j < 8; ++j) {
            int k = lane + 32 * j;
            float drv = dri[k], div = dii[k];
            float t1v = t1[k], t2v = t2[k];
            a1 += t1v * drv; b1 += t1v * div;
            a2 += t2v * drv; b2 += t2v * div;
        }
#pragma unroll
        for (int off = 16; off; off >>= 1) {
            a1 += __shfl_xor_sync(0xffffffffu, a1, off);
            b1 += __shfl_xor_sync(0xffffffffu, b1, off);
            a2 += __shfl_xor_sync(0xffffffffu, a2, off);
            b2 += __shfl_xor_sync(0xffffffffu, b2, off);
        }
        if (lane == 0) {
            stm[w]     = make_float2(a1, b1);
            stm[w + 8] = make_float2(a2, b2);
        }
    }
    __syncthreads();

    const int o  = tid & 63;
    const int b0 = tid >> 6;     // 0..3
    // Gauss 3M accumulators: A1 = sum xr*wr, A2 = sum xi*wi, A3 = sum (xr+xi)(wr+wi)
    float A1[4], A2[4], A3[4];
#pragma unroll
    for (int bb = 0; bb < 4; ++bb) { A1[bb] = 0.f; A2[bb] = 0.f; A3[bb] = 0.f; }

#pragma unroll 4
    for (int c = 0; c < CIN; ++c) {
        float2 Wv = sW[c * COUT + o];
        float ws = Wv.x + Wv.y;
#pragma unroll
        for (int bb = 0; bb < 4; ++bb) {
            float4 xv = sx4[(bb * 4 + b0) * CIN + c];
            A1[bb] += xv.x * Wv.x;
            A2[bb] += xv.y * Wv.y;
            A3[bb] += xv.z * ws;
        }
    }
#pragma unroll
    for (int bb = 0; bb < 4; ++bb) {
        int b = bb * 4 + b0;
        float yr = A1[bb] - A2[bb];
        float yi = A3[bb] - A1[bb] - A2[bb];
        float2 r = cmul(stm[b], make_float2(yr, yi));
        g_oft[((size_t)b * COUT + o) * MODES + i] = r;
    }
}

// ---------------- kernel 4: zero-padded irfft per (b, cout) ------------------
__global__ __launch_bounds__(512, 2) void inv_fft_kernel() {
    extern __shared__ float2 sh[];
    float2* U = sh;
    float2* T = sh + USIZE;
    const int tid = threadIdx.x;
    const int b = blockIdx.x >> 6;
    const int o = blockIdx.x & 63;
    const float2* of = g_oft + ((size_t)b * COUT + o) * MODES;

    load_table(T, tid);

    // Build conj(Z)[512a + m] in registers (m = tid), folding the half-complex
    // untangle. Nonzero only for a in {0..3, 12..15} (and a=4 when tid==0).
    const float2 EA[16] = {
        { 1.00000000000000f, 0.00000000000000f},
        { 0.98078528040323f, 0.19509032201613f},
        { 0.92387953251129f, 0.38268343236509f},
        { 0.83146961230255f, 0.55557023301960f},
        { 0.70710678118655f, 0.70710678118655f},
        { 0.55557023301960f, 0.83146961230255f},
        { 0.38268343236509f, 0.92387953251129f},
        { 0.19509032201613f, 0.98078528040323f},
        { 0.00000000000000f, 1.00000000000000f},
        {-0.19509032201613f, 0.98078528040323f},
        {-0.38268343236509f, 0.92387953251129f},
        {-0.55557023301960f, 0.83146961230255f},
        {-0.70710678118655f, 0.70710678118655f},
        {-0.83146961230255f, 0.55557023301960f},
        {-0.92387953251129f, 0.38268343236509f},
        {-0.98078528040323f, 0.19509032201613f}};
    float sm, cm;
    sincospif((float)tid * (1.0f / 8192.0f), &sm, &cm);    // e^{+i*pi*tid/8192}
    float2 wm = make_float2(cm, sm);

    float2 v[16];
#pragma unroll
    for (int a = 0; a < 16; ++a) {
        if (a >= 5 && a <= 11) { v[a] = make_float2(0.f, 0.f); continue; }
        int k = 512 * a + tid;
        float2 OF = make_float2(0.f, 0.f);
        float2 OC = make_float2(0.f, 0.f);
        if (k < MODES) OF = of[k];
        if (k == 0) OF.y = 0.f;                 // irfft drops Im of bin 0
        if (k >= NH - 2048) {                   // N-k <= 2048 (k>0)
            float2 t = of[NH - k];
            OC = make_float2(t.x, -t.y);
        }
        float2 A  = cadd(OF, OC);
        float2 Bd = csub(OF, OC);
        float2 w  = cmul(wm, EA[a]);            // e^{+2pi i k/16384}
        float2 Bt = cmul(w, Bd);
        v[a] = make_float2(A.x - Bt.y, -(A.y + Bt.x));   // conj(Z[k])
    }
    __syncthreads();

    // stage-1 DFT16: sparse (v[4..11] == 0) for all threads except tid 0,
    // whose v[4] (mode k = 2048) is nonzero.
    if (tid == 0) dft16(v);
    else          dft16_sparse(v);
    fft8192_tail(v, U, T, tid, true, false);   // F[n] now in U (skewed, natural)

    // coalesced store: out[2n], out[2n+1] are contiguous in outT row
    float2* ob = (float2*)(g_outT + ((size_t)b * COUT + o) * NGRID);
#pragma unroll
    for (int j = 0; j < 16; ++j) {
        int n = tid + 512 * j;
        float2 F = U[n + (n >> 4)];
        ob[n] = make_float2(F.x, -F.y);
    }
}

// ---------------- launch ------------------------------------------------------
extern "C" void kernel_launch(void* const* d_in, const int* in_sizes, int n_in,
                              void* d_out, int out_size) {
    const float* x   = (const float*)d_in[0];
    const float* te  = (const float*)d_in[1];
    const float* wr  = (const float*)d_in[2];
    const float* wi  = (const float*)d_in[3];
    const float* drw = (const float*)d_in[4];
    const float* diw = (const float*)d_in[5];
    float* out = (float*)d_out;

    const int smem = (USIZE + TSIZE) * sizeof(float2);   // 102656 bytes
    cudaFuncSetAttribute(fwd_fft_kernel, cudaFuncAttributeMaxDynamicSharedMemorySize, smem);
    cudaFuncSetAttribute(inv_fft_kernel, cudaFuncAttributeMaxDynamicSharedMemorySize, smem);

    transpose_in_kernel<<<dim3(NGRID / 64, BB), 256>>>(x);
    fwd_fft_kernel<<<BB * CIN, 512, smem>>>();
    specmul_kernel<<<MODES, 256>>>(wr, wi, te, drw, diw);
    inv_fft_kernel<<<BB * COUT, 512, smem>>>();
    transpose_out_kernel<<<dim3(NGRID / 64, BB), 256>>>(out);
}

// round 15
// speedup vs baseline: 1.7689x; 1.1704x over previous
#include <cuda_runtime.h>
#include <cstdint>

#define NGRID 16384
#define NH    8192
#define MODES 2049
#define BB    16
#define CIN   64
#define COUT  64
#define TDIM  256

#define ROW   546              // padded row stride (float2) for the 16 k1-rows
#define USIZE (16 * ROW)       // 8736 float2
#define TSIZE 4096             // twiddle table entries

// ---------------- scratch (static device globals; no allocation) -------------
__device__ float2 g_xft[(size_t)BB * MODES * CIN];   // (B, M, Cin)
__device__ float2 g_oft[(size_t)BB * COUT * MODES];  // (B, Cout, M)
__device__ float2 g_twid[TSIZE];                     // W_8192^t
__device__ float  g_xT [(size_t)BB * CIN  * NGRID];  // x transposed (B, C, N)
__device__ float  g_outT[(size_t)BB * COUT * NGRID]; // out transposed (B, C, N)

// ---------------- complex helpers -------------------------------------------
__device__ __forceinline__ float2 cmul(float2 a, float2 b) {
    return make_float2(a.x * b.x - a.y * b.y, a.x * b.y + a.y * b.x);
}
__device__ __forceinline__ float2 cadd(float2 a, float2 b) { return make_float2(a.x + b.x, a.y + b.y); }
__device__ __forceinline__ float2 csub(float2 a, float2 b) { return make_float2(a.x - b.x, a.y - b.y); }

// ---------------- register DFT-4 / DFT-16 ------------------------------------
__device__ __forceinline__ void dft4(float2& a, float2& b, float2& c, float2& d) {
    float2 t0 = cadd(a, c), t1 = csub(a, c), t2 = cadd(b, d), t3 = csub(b, d);
    a = cadd(t0, t2);
    c = csub(t0, t2);
    b = cadd(t1, make_float2(t3.y, -t3.x));   // t1 - i*t3
    d = cadd(t1, make_float2(-t3.y, t3.x));   // t1 + i*t3
}

// In: v[j] natural order. Out: X[k1 + 4*k2] stored in slot (4*k1 + k2).
#define SLOT(k) ((((k) & 3) << 2) | ((k) >> 2))

__device__ __forceinline__ void dft16_twiddle_rows(float2 v[16]) {
    const float C1 = 0.9238795325112867f, S1 = 0.3826834323650898f, R = 0.7071067811865476f;
    v[5]  = cmul(v[5],  make_float2( C1, -S1));   // W16^1
    v[6]  = cmul(v[6],  make_float2( R,  -R ));   // W16^2
    v[7]  = cmul(v[7],  make_float2( S1, -C1));   // W16^3
    v[9]  = cmul(v[9],  make_float2( R,  -R ));   // W16^2
    v[10] = make_float2(v[10].y, -v[10].x);       // W16^4 = -i
    v[11] = cmul(v[11], make_float2(-R,  -R ));   // W16^6
    v[13] = cmul(v[13], make_float2( S1, -C1));   // W16^3
    v[14] = cmul(v[14], make_float2(-R,  -R ));   // W16^6
    v[15] = cmul(v[15], make_float2(-C1,  S1));   // W16^9
#pragma unroll
    for (int k1 = 0; k1 < 4; ++k1)
        dft4(v[4 * k1], v[4 * k1 + 1], v[4 * k1 + 2], v[4 * k1 + 3]);
}

__device__ __forceinline__ void dft16(float2 v[16]) {
#pragma unroll
    for (int j2 = 0; j2 < 4; ++j2)
        dft4(v[j2], v[4 + j2], v[8 + j2], v[12 + j2]);
    dft16_twiddle_rows(v);
}

// Sparse variant: v[4..11] are known zero. Column dft4 over (a, 0, 0, d):
// out = (a+d, a+i d, a-d, a-i d).
__device__ __forceinline__ void dft16_sparse(float2 v[16]) {
#pragma unroll
    for (int j = 0; j < 4; ++j) {
        float2 a = v[j], d = v[12 + j];
        float2 id = make_float2(-d.y, d.x);     // i*d
        v[j]      = cadd(a, d);
        v[4 + j]  = cadd(a, id);
        v[8 + j]  = csub(a, d);
        v[12 + j] = csub(a, id);
    }
    dft16_twiddle_rows(v);
}

// ---------------- shared 8192-pt forward-DFT core ----------------------------
__device__ __forceinline__ void fft8192_tail(float2 v[16], float2* U,
                                             const float2* T, int tid,
                                             bool store_back, bool prune_out) {
    const int m = tid;
    // ---- stage 1 epilogue: twiddle W^{m*k}, store rows U[k*ROW + m]
    {
        float2 w = T[m];                 // W^m  (m < 512)
        float2 vw = make_float2(1.f, 0.f);
#pragma unroll
        for (int k = 0; k < 16; ++k) {
            U[k * ROW + m] = cmul(v[SLOT(k)], vw);
            vw = cmul(vw, w);
        }
    }
    __syncthreads();
    // ---- stage 2: per (k1,u): DFT16 over b, twiddle W_512^{u*q1}
    {
        const int k1 = tid >> 5, u = tid & 31;
        float2* Urow = U + k1 * ROW;
#pragma unroll
        for (int b = 0; b < 16; ++b) v[b] = Urow[32 * b + u];
        dft16(v);
        float2 w = T[16 * u];            // W_512^u
        float2 vw = make_float2(1.f, 0.f);
#pragma unroll
        for (int q1 = 0; q1 < 16; ++q1) {
            Urow[34 * q1 + u] = cmul(v[SLOT(q1)], vw);
            vw = cmul(vw, w);
        }
    }
    __syncthreads();
    // ---- stage 3: per (k1,q1,h): radix-2 combine + DFT16 over u'
    {
        const int k1 = tid >> 5, q1 = (tid >> 1) & 15, h = tid & 1;
        const float2* Urow = U + k1 * ROW + 34 * q1;
#pragma unroll
        for (int up = 0; up < 16; ++up) {
            float2 ca = Urow[up];
            float2 cb = Urow[up + 16];
            if (h == 0) v[up] = cadd(ca, cb);
            else        v[up] = cmul(csub(ca, cb), T[256 * up]);   // * W_32^{u'}
        }
        __syncthreads();                 // everyone done reading U
        dft16(v);
        if (store_back) {
            const int kb = k1 + 16 * q1 + 256 * h;
#pragma unroll
            for (int p = 0; p < 16; ++p) {
                if (prune_out && p >= 5 && p <= 11) continue;
                int k = kb + 512 * p;
                U[k + (k >> 4)] = v[SLOT(p)];
            }
            __syncthreads();
        }
    }
}

__device__ __forceinline__ void load_table(float2* T, int tid) {
#pragma unroll
    for (int j = 0; j < TSIZE / 512; ++j) {
        int t = tid + 512 * j;
        T[t] = g_twid[t];
    }
}

// ---------------- transpose kernels ------------------------------------------
__global__ __launch_bounds__(256) void transpose_in_kernel(const float* __restrict__ src) {
    __shared__ float tile[64][65];
    const int tx = threadIdx.x & 63, ty = threadIdx.x >> 6;
    const int b = blockIdx.y;
    const size_t n0 = (size_t)blockIdx.x * 64;

    if (blockIdx.y == 0 && blockIdx.x < 8) {
#pragma unroll
        for (int j = 0; j < 2; ++j) {
            int t = blockIdx.x * 512 + threadIdx.x + 256 * j;
            float s, c;
            sincospif((float)t * (-1.0f / 4096.0f), &s, &c);   // W_8192^t
            g_twid[t] = make_float2(c, s);
        }
    }

    const float* s = src + ((size_t)b * NGRID + n0) * CIN;
#pragma unroll
    for (int i = 0; i < 16; ++i) {
        int r = ty + 4 * i;
        tile[r][tx] = s[(size_t)r * CIN + tx];
    }
    __syncthreads();
    float* d = g_xT + (size_t)b * CIN * NGRID + n0;
#pragma unroll
    for (int i = 0; i < 16; ++i) {
        int c = ty + 4 * i;
        d[(size_t)c * NGRID + tx] = tile[tx][c];
    }
}

__global__ __launch_bounds__(256) void transpose_out_kernel(float* __restrict__ dst) {
    __shared__ float tile[64][65];
    const int tx = threadIdx.x & 63, ty = threadIdx.x >> 6;
    const int b = blockIdx.y;
    const size_t n0 = (size_t)blockIdx.x * 64;
    const float* s = g_outT + (size_t)b * COUT * NGRID + n0;
#pragma unroll
    for (int i = 0; i < 16; ++i) {
        int c = ty + 4 * i;
        tile[c][tx] = s[(size_t)c * NGRID + tx];
    }
    __syncthreads();
    float* d = dst + ((size_t)b * NGRID + n0) * COUT;
#pragma unroll
    for (int i = 0; i < 16; ++i) {
        int r = ty + 4 * i;
        d[(size_t)r * COUT + tx] = tile[tx][r];
    }
}

// ---------------- kernel 2: forward rfft per (b, cin) ------------------------
__global__ __launch_bounds__(512, 2) void fwd_fft_kernel() {
    extern __shared__ float2 sh[];
    float2* U = sh;
    float2* T = sh + USIZE;
    const int tid = threadIdx.x;
    const int b = blockIdx.x >> 6;
    const int c = blockIdx.x & 63;
    const float2* xb = (const float2*)(g_xT + ((size_t)b * CIN + c) * NGRID);

    float2 v[16];
#pragma unroll
    for (int a = 0; a < 16; ++a) v[a] = xb[512 * a + tid];
    load_table(T, tid);
    __syncthreads();

    dft16(v);
    fft8192_tail(v, U, T, tid, true, true);

    // real-FFT untangle, forward norm (1/N)
    const float invN = 1.0f / 16384.0f;
    const float2 EJ[5] = {
        {1.f, 0.f},
        {0.98078528040323f, -0.19509032201613f},
        {0.92387953251129f, -0.38268343236509f},
        {0.83146961230255f, -0.55557023301960f},
        {0.70710678118655f, -0.70710678118655f}};
    float sm, cm;
    sincospif((float)tid * (-1.0f / 8192.0f), &sm, &cm);  // e^{-i*pi*tid/8192}
    float2 wm = make_float2(cm, sm);
#pragma unroll
    for (int j = 0; j < 5; ++j) {
        int k = tid + 512 * j;
        if (k > 2048) break;
        int km = (NH - k) & (NH - 1);
        float2 Zk = U[k + (k >> 4)];
        float2 Zc = U[km + (km >> 4)];
        float2 Zcc = make_float2(Zc.x, -Zc.y);
        float2 E = make_float2(0.5f * (Zk.x + Zcc.x), 0.5f * (Zk.y + Zcc.y));
        float2 Od = csub(Zk, Zcc);
        float2 O = make_float2(0.5f * Od.y, -0.5f * Od.x);  // -i/2 * Od
        float2 w = cmul(wm, EJ[j]);                          // e^{-2pi i k/16384}
        float2 X = cadd(E, cmul(w, O));
        g_xft[((size_t)b * MODES + k) * CIN + c] = make_float2(X.x * invN, X.y * invN);
    }
}

// ---------------- kernel 3: tf32 tensor-core specmul + tmod ------------------
// Per mode i: Y(16x64) = X(16x64) * W(64x64) complex, scaled by t_mod[b,i].
// mma.sync m16n8k8 tf32: 8 warps = 8 N-tiles; accumulators P=XrWr, Q=XiWi,
// I=XrWi+XiWr; Yr=P-Q, Yi=I.
#define XLD 68
#define WLD 68

__device__ __forceinline__ float to_tf32(float x) {
    float r;
    asm("cvt.rna.tf32.f32 %0, %1;" : "=f"(r) : "f"(x));
    return r;
}
__device__ __forceinline__ void mma_tf32(float d[4], uint32_t a0, uint32_t a1,
                                         uint32_t a2, uint32_t a3,
                                         uint32_t b0, uint32_t b1) {
    asm volatile(
        "mma.sync.aligned.m16n8k8.row.col.f32.tf32.tf32.f32 "
        "{%0,%1,%2,%3}, {%4,%5,%6,%7}, {%8,%9}, {%0,%1,%2,%3};"
        : "+f"(d[0]), "+f"(d[1]), "+f"(d[2]), "+f"(d[3])
        : "r"(a0), "r"(a1), "r"(a2), "r"(a3), "r"(b0), "r"(b1));
}

__global__ __launch_bounds__(256) void specmul_kernel(const float* __restrict__ wr,
                                                      const float* __restrict__ wi,
                                                      const float* __restrict__ te,
                                                      const float* __restrict__ dr,
                                                      const float* __restrict__ di) {
    __shared__ float sXr[BB * XLD];      // [b][c], tf32-rounded
    __shared__ float sXi[BB * XLD];
    __shared__ float sWr[CIN * WLD];     // [c][o], tf32-rounded
    __shared__ float sWi[CIN * WLD];
    __shared__ float2 stm[BB];
    const int i   = blockIdx.x;
    const int tid = threadIdx.x;
    const int w   = tid >> 5, lane = tid & 31;
    const int gid = lane >> 2, tig = lane & 3;

    // ---- fill W (tf32-rounded), padded [c][o] layout
    const float4* wrb = (const float4*)(wr + (size_t)i * CIN * COUT);
    const float4* wib = (const float4*)(wi + (size_t)i * CIN * COUT);
#pragma unroll
    for (int t = 0; t < 4; ++t) {
        int idx4 = tid + 256 * t;            // < 1024
        float4 r4 = wrb[idx4];
        float4 i4 = wib[idx4];
        int l = idx4 * 4;
        int c = l >> 6, o = l & 63;
        float4* dr4 = (float4*)&sWr[c * WLD + o];
        float4* di4 = (float4*)&sWi[c * WLD + o];
        *dr4 = make_float4(to_tf32(r4.x), to_tf32(r4.y), to_tf32(r4.z), to_tf32(r4.w));
        *di4 = make_float4(to_tf32(i4.x), to_tf32(i4.y), to_tf32(i4.z), to_tf32(i4.w));
    }
    // ---- fill X (tf32-rounded)
#pragma unroll
    for (int t = 0; t < 4; ++t) {
        int idx = tid + 256 * t;             // < 1024
        int b = idx >> 6, c = idx & 63;
        float2 xv = g_xft[((size_t)b * MODES + i) * CIN + c];
        sXr[b * XLD + c] = to_tf32(xv.x);
        sXi[b * XLD + c] = to_tf32(xv.y);
    }

    // ---- t_mod: warp w computes stm[w], stm[w+8]
    {
        const float* dri = dr + (size_t)i * TDIM;
        const float* dii = di + (size_t)i * TDIM;
        const float* t1 = te + w * TDIM;
        const float* t2 = te + (w + 8) * TDIM;
        float a1 = 0.f, b1 = 0.f, a2 = 0.f, b2 = 0.f;
#pragma unroll
        for (int j = 0; j < 8; ++j) {
            int k = lane + 32 * j;
            float drv = dri[k], div = dii[k];
            float t1v = t1[k], t2v = t2[k];
            a1 += t1v * drv; b1 += t1v * div;
            a2 += t2v * drv; b2 += t2v * div;
        }
#pragma unroll
        for (int off = 16; off; off >>= 1) {
            a1 += __shfl_xor_sync(0xffffffffu, a1, off);
            b1 += __shfl_xor_sync(0xffffffffu, b1, off);
            a2 += __shfl_xor_sync(0xffffffffu, a2, off);
            b2 += __shfl_xor_sync(0xffffffffu, b2, off);
        }
        if (lane == 0) {
            stm[w]     = make_float2(a1, b1);
            stm[w + 8] = make_float2(a2, b2);
        }
    }
    __syncthreads();

    const uint32_t* uXr = (const uint32_t*)sXr;
    const uint32_t* uXi = (const uint32_t*)sXi;
    const uint32_t* uWr = (const uint32_t*)sWr;
    const uint32_t* uWi = (const uint32_t*)sWi;

    float P[4] = {0.f, 0.f, 0.f, 0.f};
    float Q[4] = {0.f, 0.f, 0.f, 0.f};
    float I4[4] = {0.f, 0.f, 0.f, 0.f};

    const int ocol = w * 8 + gid;            // B fragment column
#pragma unroll
    for (int k8 = 0; k8 < 8; ++k8) {
        int ka = k8 * 8 + tig;
        uint32_t ar0 = uXr[gid * XLD + ka];
        uint32_t ar1 = uXr[(gid + 8) * XLD + ka];
        uint32_t ar2 = uXr[gid * XLD + ka + 4];
        uint32_t ar3 = uXr[(gid + 8) * XLD + ka + 4];
        uint32_t ai0 = uXi[gid * XLD + ka];
        uint32_t ai1 = uXi[(gid + 8) * XLD + ka];
        uint32_t ai2 = uXi[gid * XLD + ka + 4];
        uint32_t ai3 = uXi[(gid + 8) * XLD + ka + 4];
        uint32_t br0 = uWr[(k8 * 8 + tig) * WLD + ocol];
        uint32_t br1 = uWr[(k8 * 8 + tig + 4) * WLD + ocol];
        uint32_t bi0 = uWi[(k8 * 8 + tig) * WLD + ocol];
        uint32_t bi1 = uWi[(k8 * 8 + tig + 4) * WLD + ocol];
        mma_tf32(P,  ar0, ar1, ar2, ar3, br0, br1);
        mma_tf32(Q,  ai0, ai1, ai2, ai3, bi0, bi1);
        mma_tf32(I4, ar0, ar1, ar2, ar3, bi0, bi1);
        mma_tf32(I4, ai0, ai1, ai2, ai3, br0, br1);
    }

    // ---- epilogue: Yr = P-Q, Yi = I; scale by tmod; store
    float2 t_lo = stm[gid], t_hi = stm[gid + 8];
    const int o0 = w * 8 + 2 * tig, o1 = o0 + 1;
    {
        float2 y = make_float2(P[0] - Q[0], I4[0]);
        g_oft[((size_t)gid * COUT + o0) * MODES + i] = cmul(t_lo, y);
    }
    {
        float2 y = make_float2(P[1] - Q[1], I4[1]);
        g_oft[((size_t)gid * COUT + o1) * MODES + i] = cmul(t_lo, y);
    }
    {
        float2 y = make_float2(P[2] - Q[2], I4[2]);
        g_oft[((size_t)(gid + 8) * COUT + o0) * MODES + i] = cmul(t_hi, y);
    }
    {
        float2 y = make_float2(P[3] - Q[3], I4[3]);
        g_oft[((size_t)(gid + 8) * COUT + o1) * MODES + i] = cmul(t_hi, y);
    }
}

// ---------------- kernel 4: zero-padded irfft per (b, cout) ------------------
__global__ __launch_bounds__(512, 2) void inv_fft_kernel() {
    extern __shared__ float2 sh[];
    float2* U = sh;
    float2* T = sh + USIZE;
    const int tid = threadIdx.x;
    const int b = blockIdx.x >> 6;
    const int o = blockIdx.x & 63;
    const float2* of = g_oft + ((size_t)b * COUT + o) * MODES;

    load_table(T, tid);

    const float2 EA[16] = {
        { 1.00000000000000f, 0.00000000000000f},
        { 0.98078528040323f, 0.19509032201613f},
        { 0.92387953251129f, 0.38268343236509f},
        { 0.83146961230255f, 0.55557023301960f},
        { 0.70710678118655f, 0.70710678118655f},
        { 0.55557023301960f, 0.83146961230255f},
        { 0.38268343236509f, 0.92387953251129f},
        { 0.19509032201613f, 0.98078528040323f},
        { 0.00000000000000f, 1.00000000000000f},
        {-0.19509032201613f, 0.98078528040323f},
        {-0.38268343236509f, 0.92387953251129f},
        {-0.55557023301960f, 0.83146961230255f},
        {-0.70710678118655f, 0.70710678118655f},
        {-0.83146961230255f, 0.55557023301960f},
        {-0.92387953251129f, 0.38268343236509f},
        {-0.98078528040323f, 0.19509032201613f}};
    float sm, cm;
    sincospif((float)tid * (1.0f / 8192.0f), &sm, &cm);    // e^{+i*pi*tid/8192}
    float2 wm = make_float2(cm, sm);

    float2 v[16];
#pragma unroll
    for (int a = 0; a < 16; ++a) {
        if (a >= 5 && a <= 11) { v[a] = make_float2(0.f, 0.f); continue; }
        int k = 512 * a + tid;
        float2 OF = make_float2(0.f, 0.f);
        float2 OC = make_float2(0.f, 0.f);
        if (k < MODES) OF = of[k];
        if (k == 0) OF.y = 0.f;                 // irfft drops Im of bin 0
        if (k >= NH - 2048) {                   // N-k <= 2048 (k>0)
            float2 t = of[NH - k];
            OC = make_float2(t.x, -t.y);
        }
        float2 A  = cadd(OF, OC);
        float2 Bd = csub(OF, OC);
        float2 w  = cmul(wm, EA[a]);            // e^{+2pi i k/16384}
        float2 Bt = cmul(w, Bd);
        v[a] = make_float2(A.x - Bt.y, -(A.y + Bt.x));   // conj(Z[k])
    }
    __syncthreads();

    if (tid == 0) dft16(v);
    else          dft16_sparse(v);
    fft8192_tail(v, U, T, tid, true, false);

    float2* ob = (float2*)(g_outT + ((size_t)b * COUT + o) * NGRID);
#pragma unroll
    for (int j = 0; j < 16; ++j) {
        int n = tid + 512 * j;
        float2 F = U[n + (n >> 4)];
        ob[n] = make_float2(F.x, -F.y);
    }
}

// ---------------- launch ------------------------------------------------------
extern "C" void kernel_launch(void* const* d_in, const int* in_sizes, int n_in,
                              void* d_out, int out_size) {
    const float* x   = (const float*)d_in[0];
    const float* te  = (const float*)d_in[1];
    const float* wr  = (const float*)d_in[2];
    const float* wi  = (const float*)d_in[3];
    const float* drw = (const float*)d_in[4];
    const float* diw = (const float*)d_in[5];
    float* out = (float*)d_out;

    const int smem = (USIZE + TSIZE) * sizeof(float2);   // 102656 bytes
    cudaFuncSetAttribute(fwd_fft_kernel, cudaFuncAttributeMaxDynamicSharedMemorySize, smem);
    cudaFuncSetAttribute(inv_fft_kernel, cudaFuncAttributeMaxDynamicSharedMemorySize, smem);

    transpose_in_kernel<<<dim3(NGRID / 64, BB), 256>>>(x);
    fwd_fft_kernel<<<BB * CIN, 512, smem>>>();
    specmul_kernel<<<MODES, 256>>>(wr, wi, te, drw, diw);
    inv_fft_kernel<<<BB * COUT, 512, smem>>>();
    transpose_out_kernel<<<dim3(NGRID / 64, BB), 256>>>(out);
}

// round 17
// speedup vs baseline: 1.8229x; 1.0305x over previous
#include <cuda_runtime.h>
#include <cstdint>

#define NGRID 16384
#define NH    8192
#define MODES 2049
#define BB    16
#define CIN   64
#define COUT  64
#define TDIM  256

#define ROW   546              // padded row stride (float2) for the 16 k1-rows
#define USIZE (16 * ROW)       // 8736 float2
#define TSIZE 512              // twiddle table entries (W_8192^t, t<512)

// ---------------- scratch (static device globals; no allocation) -------------
__device__ float2 g_xft[(size_t)BB * CIN * MODES];   // (B, Cin, M)
__device__ float2 g_oft[(size_t)BB * COUT * MODES];  // (B, Cout, M)
__device__ float2 g_twid[TSIZE];                     // W_8192^t
__device__ float  g_xT [(size_t)BB * CIN  * NGRID];  // x transposed (B, C, N)
__device__ float  g_outT[(size_t)BB * COUT * NGRID]; // out transposed (B, C, N)

// ---------------- complex helpers -------------------------------------------
__device__ __forceinline__ float2 cmul(float2 a, float2 b) {
    return make_float2(a.x * b.x - a.y * b.y, a.x * b.y + a.y * b.x);
}
__device__ __forceinline__ float2 cadd(float2 a, float2 b) { return make_float2(a.x + b.x, a.y + b.y); }
__device__ __forceinline__ float2 csub(float2 a, float2 b) { return make_float2(a.x - b.x, a.y - b.y); }

// ---------------- register DFT-4 / DFT-16 ------------------------------------
__device__ __forceinline__ void dft4(float2& a, float2& b, float2& c, float2& d) {
    float2 t0 = cadd(a, c), t1 = csub(a, c), t2 = cadd(b, d), t3 = csub(b, d);
    a = cadd(t0, t2);
    c = csub(t0, t2);
    b = cadd(t1, make_float2(t3.y, -t3.x));   // t1 - i*t3
    d = cadd(t1, make_float2(-t3.y, t3.x));   // t1 + i*t3
}

// In: v[j] natural order. Out: X[k1 + 4*k2] stored in slot (4*k1 + k2).
#define SLOT(k) ((((k) & 3) << 2) | ((k) >> 2))

__device__ __forceinline__ void dft16_twiddle_rows(float2 v[16]) {
    const float C1 = 0.9238795325112867f, S1 = 0.3826834323650898f, R = 0.7071067811865476f;
    v[5]  = cmul(v[5],  make_float2( C1, -S1));   // W16^1
    v[6]  = cmul(v[6],  make_float2( R,  -R ));   // W16^2
    v[7]  = cmul(v[7],  make_float2( S1, -C1));   // W16^3
    v[9]  = cmul(v[9],  make_float2( R,  -R ));   // W16^2
    v[10] = make_float2(v[10].y, -v[10].x);       // W16^4 = -i
    v[11] = cmul(v[11], make_float2(-R,  -R ));   // W16^6
    v[13] = cmul(v[13], make_float2( S1, -C1));   // W16^3
    v[14] = cmul(v[14], make_float2(-R,  -R ));   // W16^6
    v[15] = cmul(v[15], make_float2(-C1,  S1));   // W16^9
#pragma unroll
    for (int k1 = 0; k1 < 4; ++k1)
        dft4(v[4 * k1], v[4 * k1 + 1], v[4 * k1 + 2], v[4 * k1 + 3]);
}

__device__ __forceinline__ void dft16(float2 v[16]) {
#pragma unroll
    for (int j2 = 0; j2 < 4; ++j2)
        dft4(v[j2], v[4 + j2], v[8 + j2], v[12 + j2]);
    dft16_twiddle_rows(v);
}

// Sparse variant: v[4..11] are known zero. Column dft4 over (a, 0, 0, d):
// out = (a+d, a+i d, a-d, a-i d).
__device__ __forceinline__ void dft16_sparse(float2 v[16]) {
#pragma unroll
    for (int j = 0; j < 4; ++j) {
        float2 a = v[j], d = v[12 + j];
        float2 id = make_float2(-d.y, d.x);     // i*d
        v[j]      = cadd(a, d);
        v[4 + j]  = cadd(a, id);
        v[8 + j]  = csub(a, d);
        v[12 + j] = csub(a, id);
    }
    dft16_twiddle_rows(v);
}

// ---------------- shared 8192-pt forward-DFT core ----------------------------
// On entry: v holds stage-1 dft16 outputs for z[512*a + m], m = tid.
// T[t] = W_8192^t, t<512 (stage-3 twiddles are compile-time constants).
__device__ __forceinline__ void fft8192_tail(float2 v[16], float2* U,
                                             const float2* T, int tid,
                                             bool store_back, bool prune_out) {
    // W_32^u (stage-3 twiddles)
    const float2 W32[16] = {
        { 1.00000000000000f,  0.00000000000000f},
        { 0.98078528040323f, -0.19509032201613f},
        { 0.92387953251129f, -0.38268343236509f},
        { 0.83146961230255f, -0.55557023301960f},
        { 0.70710678118655f, -0.70710678118655f},
        { 0.55557023301960f, -0.83146961230255f},
        { 0.38268343236509f, -0.92387953251129f},
        { 0.19509032201613f, -0.98078528040323f},
        { 0.00000000000000f, -1.00000000000000f},
        {-0.19509032201613f, -0.98078528040323f},
        {-0.38268343236509f, -0.92387953251129f},
        {-0.55557023301960f, -0.83146961230255f},
        {-0.70710678118655f, -0.70710678118655f},
        {-0.83146961230255f, -0.55557023301960f},
        {-0.92387953251129f, -0.38268343236509f},
        {-0.98078528040323f, -0.19509032201613f}};
    const int m = tid;
    // ---- stage 1 epilogue: twiddle W^{m*k}, store rows U[k*ROW + m]
    {
        float2 w = T[m];                 // W^m  (m < 512)
        float2 vw = make_float2(1.f, 0.f);
#pragma unroll
        for (int k = 0; k < 16; ++k) {
            U[k * ROW + m] = cmul(v[SLOT(k)], vw);
            vw = cmul(vw, w);
        }
    }
    __syncthreads();
    // ---- stage 2: per (k1,u): DFT16 over b, twiddle W_512^{u*q1}
    {
        const int k1 = tid >> 5, u = tid & 31;
        float2* Urow = U + k1 * ROW;
#pragma unroll
        for (int b = 0; b < 16; ++b) v[b] = Urow[32 * b + u];
        dft16(v);
        float2 w = T[16 * u];            // W_512^u
        float2 vw = make_float2(1.f, 0.f);
#pragma unroll
        for (int q1 = 0; q1 < 16; ++q1) {
            Urow[34 * q1 + u] = cmul(v[SLOT(q1)], vw);
            vw = cmul(vw, w);
        }
    }
    __syncthreads();
    // ---- stage 3: per (k1,q1,h): radix-2 combine + DFT16 over u'
    {
        const int k1 = tid >> 5, q1 = (tid >> 1) & 15, h = tid & 1;
        const float2* Urow = U + k1 * ROW + 34 * q1;
#pragma unroll
        for (int up = 0; up < 16; ++up) {
            float2 ca = Urow[up];
            float2 cb = Urow[up + 16];
            if (h == 0) v[up] = cadd(ca, cb);
            else        v[up] = cmul(csub(ca, cb), W32[up]);   // * W_32^{u'}
        }
        __syncthreads();                 // everyone done reading U
        dft16(v);
        if (store_back) {
            const int kb = k1 + 16 * q1 + 256 * h;
#pragma unroll
            for (int p = 0; p < 16; ++p) {
                if (prune_out && p >= 5 && p <= 11) continue;
                int k = kb + 512 * p;
                U[k + (k >> 4)] = v[SLOT(p)];
            }
            __syncthreads();
        }
    }
}

__device__ __forceinline__ void load_table(float2* T, int tid) {
    if (tid < TSIZE) T[tid] = g_twid[tid];
}

// ---------------- transpose kernels ------------------------------------------
__global__ __launch_bounds__(256) void transpose_in_kernel(const float* __restrict__ src) {
    __shared__ float tile[64][65];
    const int tx = threadIdx.x & 63, ty = threadIdx.x >> 6;
    const int b = blockIdx.y;
    const size_t n0 = (size_t)blockIdx.x * 64;

    if (blockIdx.y == 0 && blockIdx.x == 0) {
#pragma unroll
        for (int j = 0; j < 2; ++j) {
            int t = threadIdx.x + 256 * j;
            float s, c;
            sincospif((float)t * (-1.0f / 4096.0f), &s, &c);   // W_8192^t
            g_twid[t] = make_float2(c, s);
        }
    }

    const float* s = src + ((size_t)b * NGRID + n0) * CIN;
#pragma unroll
    for (int i = 0; i < 16; ++i) {
        int r = ty + 4 * i;
        tile[r][tx] = s[(size_t)r * CIN + tx];
    }
    __syncthreads();
    float* d = g_xT + (size_t)b * CIN * NGRID + n0;
#pragma unroll
    for (int i = 0; i < 16; ++i) {
        int c = ty + 4 * i;
        d[(size_t)c * NGRID + tx] = tile[tx][c];
    }
}

__global__ __launch_bounds__(256) void transpose_out_kernel(float* __restrict__ dst) {
    __shared__ float tile[64][65];
    const int tx = threadIdx.x & 63, ty = threadIdx.x >> 6;
    const int b = blockIdx.y;
    const size_t n0 = (size_t)blockIdx.x * 64;
    const float* s = g_outT + (size_t)b * COUT * NGRID + n0;
#pragma unroll
    for (int i = 0; i < 16; ++i) {
        int c = ty + 4 * i;
        tile[c][tx] = s[(size_t)c * NGRID + tx];
    }
    __syncthreads();
    float* d = dst + ((size_t)b * NGRID + n0) * COUT;
#pragma unroll
    for (int i = 0; i < 16; ++i) {
        int r = ty + 4 * i;
        d[(size_t)r * COUT + tx] = tile[tx][r];
    }
}

// ---------------- kernel 2: forward rfft per (b, cin) ------------------------
__global__ __launch_bounds__(512, 2) void fwd_fft_kernel() {
    extern __shared__ float2 sh[];
    float2* U = sh;
    float2* T = sh + USIZE;
    const int tid = threadIdx.x;
    const int b = blockIdx.x >> 6;
    const int c = blockIdx.x & 63;
    const float2* xb = (const float2*)(g_xT + ((size_t)b * CIN + c) * NGRID);

    float2 v[16];
#pragma unroll
    for (int a = 0; a < 16; ++a) v[a] = xb[512 * a + tid];
    load_table(T, tid);
    __syncthreads();

    dft16(v);
    fft8192_tail(v, U, T, tid, true, true);

    // real-FFT untangle, forward norm (1/N); coalesced writes (k contiguous)
    const float invN = 1.0f / 16384.0f;
    const float2 EJ[5] = {
        {1.f, 0.f},
        {0.98078528040323f, -0.19509032201613f},
        {0.92387953251129f, -0.38268343236509f},
        {0.83146961230255f, -0.55557023301960f},
        {0.70710678118655f, -0.70710678118655f}};
    float sm, cm;
    sincospif((float)tid * (-1.0f / 8192.0f), &sm, &cm);  // e^{-i*pi*tid/8192}
    float2 wm = make_float2(cm, sm);
    float2* xout = g_xft + ((size_t)b * CIN + c) * MODES;
#pragma unroll
    for (int j = 0; j < 5; ++j) {
        int k = tid + 512 * j;
        if (k > 2048) break;
        int km = (NH - k) & (NH - 1);
        float2 Zk = U[k + (k >> 4)];
        float2 Zc = U[km + (km >> 4)];
        float2 Zcc = make_float2(Zc.x, -Zc.y);
        float2 E = make_float2(0.5f * (Zk.x + Zcc.x), 0.5f * (Zk.y + Zcc.y));
        float2 Od = csub(Zk, Zcc);
        float2 O = make_float2(0.5f * Od.y, -0.5f * Od.x);  // -i/2 * Od
        float2 w = cmul(wm, EJ[j]);                          // e^{-2pi i k/16384}
        float2 X = cadd(E, cmul(w, O));
        xout[k] = make_float2(X.x * invN, X.y * invN);
    }
}

// ---------------- kernel 3: tf32 tensor-core specmul + tmod ------------------
#define XLD 68
#define WLD 68

__device__ __forceinline__ float to_tf32(float x) {
    float r;
    asm("cvt.rna.tf32.f32 %0, %1;" : "=f"(r) : "f"(x));
    return r;
}
__device__ __forceinline__ void mma_tf32(float d[4], uint32_t a0, uint32_t a1,
                                         uint32_t a2, uint32_t a3,
                                         uint32_t b0, uint32_t b1) {
    asm volatile(
        "mma.sync.aligned.m16n8k8.row.col.f32.tf32.tf32.f32 "
        "{%0,%1,%2,%3}, {%4,%5,%6,%7}, {%8,%9}, {%0,%1,%2,%3};"
        : "+f"(d[0]), "+f"(d[1]), "+f"(d[2]), "+f"(d[3])
        : "r"(a0), "r"(a1), "r"(a2), "r"(a3), "r"(b0), "r"(b1));
}

__global__ __launch_bounds__(256) void specmul_kernel(const float* __restrict__ wr,
                                                      const float* __restrict__ wi,
                                                      const float* __restrict__ te,
                                                      const float* __restrict__ dr,
                                                      const float* __restrict__ di) {
    __shared__ float sXr[BB * XLD];      // [b][c], tf32-rounded
    __shared__ float sXi[BB * XLD];
    __shared__ float sWr[CIN * WLD];     // [c][o], tf32-rounded
    __shared__ float sWi[CIN * WLD];
    __shared__ float2 stm[BB];
    const int i   = blockIdx.x;
    const int tid = threadIdx.x;
    const int w   = tid >> 5, lane = tid & 31;
    const int gid = lane >> 2, tig = lane & 3;

    // ---- fill W (tf32-rounded), padded [c][o] layout
    const float4* wrb = (const float4*)(wr + (size_t)i * CIN * COUT);
    const float4* wib = (const float4*)(wi + (size_t)i * CIN * COUT);
#pragma unroll
    for (int t = 0; t < 4; ++t) {
        int idx4 = tid + 256 * t;            // < 1024
        float4 r4 = wrb[idx4];
        float4 i4 = wib[idx4];
        int l = idx4 * 4;
        int c = l >> 6, o = l & 63;
        float4* dr4 = (float4*)&sWr[c * WLD + o];
        float4* di4 = (float4*)&sWi[c * WLD + o];
        *dr4 = make_float4(to_tf32(r4.x), to_tf32(r4.y), to_tf32(r4.z), to_tf32(r4.w));
        *di4 = make_float4(to_tf32(i4.x), to_tf32(i4.y), to_tf32(i4.z), to_tf32(i4.w));
    }
    // ---- fill X (tf32-rounded); gathered reads (stride MODES), L2-local
#pragma unroll
    for (int t = 0; t < 4; ++t) {
        int idx = tid + 256 * t;             // < 1024
        int b = idx >> 6, c = idx & 63;
        float2 xv = g_xft[((size_t)b * CIN + c) * MODES + i];
        sXr[b * XLD + c] = to_tf32(xv.x);
        sXi[b * XLD + c] = to_tf32(xv.y);
    }

    // ---- t_mod: warp w computes stm[w], stm[w+8]
    {
        const float* dri = dr + (size_t)i * TDIM;
        const float* dii = di + (size_t)i * TDIM;
        const float* t1 = te + w * TDIM;
        const float* t2 = te + (w + 8) * TDIM;
        float a1 = 0.f, b1 = 0.f, a2 = 0.f, b2 = 0.f;
#pragma unroll
        for (int j = 0; j < 8; ++j) {
            int k = lane + 32 * j;
            float drv = dri[k], div = dii[k];
            float t1v = t1[k], t2v = t2[k];
            a1 += t1v * drv; b1 += t1v * div;
            a2 += t2v * drv; b2 += t2v * div;
        }
#pragma unroll
        for (int off = 16; off; off >>= 1) {
            a1 += __shfl_xor_sync(0xffffffffu, a1, off);
            b1 += __shfl_xor_sync(0xffffffffu, b1, off);
            a2 += __shfl_xor_sync(0xffffffffu, a2, off);
            b2 += __shfl_xor_sync(0xffffffffu, b2, off);
        }
        if (lane == 0) {
            stm[w]     = make_float2(a1, b1);
            stm[w + 8] = make_float2(a2, b2);
        }
    }
    __syncthreads();

    const uint32_t* uXr = (const uint32_t*)sXr;
    const uint32_t* uXi = (const uint32_t*)sXi;
    const uint32_t* uWr = (const uint32_t*)sWr;
    const uint32_t* uWi = (const uint32_t*)sWi;

    float P[4] = {0.f, 0.f, 0.f, 0.f};
    float Q[4] = {0.f, 0.f, 0.f, 0.f};
    float I4[4] = {0.f, 0.f, 0.f, 0.f};

    const int ocol = w * 8 + gid;            // B fragment column
#pragma unroll
    for (int k8 = 0; k8 < 8; ++k8) {
        int ka = k8 * 8 + tig;
        uint32_t ar0 = uXr[gid * XLD + ka];
        uint32_t ar1 = uXr[(gid + 8) * XLD + ka];
        uint32_t ar2 = uXr[gid * XLD + ka + 4];
        uint32_t ar3 = uXr[(gid + 8) * XLD + ka + 4];
        uint32_t ai0 = uXi[gid * XLD + ka];
        uint32_t ai1 = uXi[(gid + 8) * XLD + ka];
        uint32_t ai2 = uXi[gid * XLD + ka + 4];
        uint32_t ai3 = uXi[(gid + 8) * XLD + ka + 4];
        uint32_t br0 = uWr[(k8 * 8 + tig) * WLD + ocol];
        uint32_t br1 = uWr[(k8 * 8 + tig + 4) * WLD + ocol];
        uint32_t bi0 = uWi[(k8 * 8 + tig) * WLD + ocol];
        uint32_t bi1 = uWi[(k8 * 8 + tig + 4) * WLD + ocol];
        mma_tf32(P,  ar0, ar1, ar2, ar3, br0, br1);
        mma_tf32(Q,  ai0, ai1, ai2, ai3, bi0, bi1);
        mma_tf32(I4, ar0, ar1, ar2, ar3, bi0, bi1);
        mma_tf32(I4, ai0, ai1, ai2, ai3, br0, br1);
    }

    // ---- epilogue: Yr = P-Q, Yi = I; scale by tmod; store
    float2 t_lo = stm[gid], t_hi = stm[gid + 8];
    const int o0 = w * 8 + 2 * tig, o1 = o0 + 1;
    {
        float2 y = make_float2(P[0] - Q[0], I4[0]);
        g_oft[((size_t)gid * COUT + o0) * MODES + i] = cmul(t_lo, y);
    }
    {
        float2 y = make_float2(P[1] - Q[1], I4[1]);
        g_oft[((size_t)gid * COUT + o1) * MODES + i] = cmul(t_lo, y);
    }
    {
        float2 y = make_float2(P[2] - Q[2], I4[2]);
        g_oft[((size_t)(gid + 8) * COUT + o0) * MODES + i] = cmul(t_hi, y);
    }
    {
        float2 y = make_float2(P[3] - Q[3], I4[3]);
        g_oft[((size_t)(gid + 8) * COUT + o1) * MODES + i] = cmul(t_hi, y);
    }
}

// ---------------- kernel 4: zero-padded irfft per (b, cout) ------------------
__global__ __launch_bounds__(512, 2) void inv_fft_kernel() {
    extern __shared__ float2 sh[];
    float2* U = sh;
    float2* T = sh + USIZE;
    const int tid = threadIdx.x;
    const int b = blockIdx.x >> 6;
    const int o = blockIdx.x & 63;
    const float2* of = g_oft + ((size_t)b * COUT + o) * MODES;

    load_table(T, tid);

    const float2 EA[16] = {
        { 1.00000000000000f, 0.00000000000000f},
        { 0.98078528040323f, 0.19509032201613f},
        { 0.92387953251129f, 0.38268343236509f},
        { 0.83146961230255f, 0.55557023301960f},
        { 0.70710678118655f, 0.70710678118655f},
        { 0.55557023301960f, 0.83146961230255f},
        { 0.38268343236509f, 0.92387953251129f},
        { 0.19509032201613f, 0.98078528040323f},
        { 0.00000000000000f, 1.00000000000000f},
        {-0.19509032201613f, 0.98078528040323f},
        {-0.38268343236509f, 0.92387953251129f},
        {-0.55557023301960f, 0.83146961230255f},
        {-0.70710678118655f, 0.70710678118655f},
        {-0.83146961230255f, 0.55557023301960f},
        {-0.92387953251129f, 0.38268343236509f},
        {-0.98078528040323f, 0.19509032201613f}};
    float sm, cm;
    sincospif((float)tid * (1.0f / 8192.0f), &sm, &cm);    // e^{+i*pi*tid/8192}
    float2 wm = make_float2(cm, sm);

    float2 v[16];
#pragma unroll
    for (int a = 0; a < 16; ++a) {
        if (a >= 5 && a <= 11) { v[a] = make_float2(0.f, 0.f); continue; }
        int k = 512 * a + tid;
        float2 OF = make_float2(0.f, 0.f);
        float2 OC = make_float2(0.f, 0.f);
        if (k < MODES) OF = of[k];
        if (k == 0) OF.y = 0.f;                 // irfft drops Im of bin 0
        if (k >= NH - 2048) {                   // N-k <= 2048 (k>0)
            float2 t = of[NH - k];
            OC = make_float2(t.x, -t.y);
        }
        float2 A  = cadd(OF, OC);
        float2 Bd = csub(OF, OC);
        float2 w  = cmul(wm, EA[a]);            // e^{+2pi i k/16384}
        float2 Bt = cmul(w, Bd);
        v[a] = make_float2(A.x - Bt.y, -(A.y + Bt.x));   // conj(Z[k])
    }
    __syncthreads();

    if (tid == 0) dft16(v);
    else          dft16_sparse(v);
    fft8192_tail(v, U, T, tid, true, false);

    float2* ob = (float2*)(g_outT + ((size_t)b * COUT + o) * NGRID);
#pragma unroll
    for (int j = 0; j < 16; ++j) {
        int n = tid + 512 * j;
        float2 F = U[n + (n >> 4)];
        ob[n] = make_float2(F.x, -F.y);
    }
}

// ---------------- launch ------------------------------------------------------
extern "C" void kernel_launch(void* const* d_in, const int* in_sizes, int n_in,
                              void* d_out, int out_size) {
    const float* x   = (const float*)d_in[0];
    const float* te  = (const float*)d_in[1];
    const float* wr  = (const float*)d_in[2];
    const float* wi  = (const float*)d_in[3];
    const float* drw = (const float*)d_in[4];
    const float* diw = (const float*)d_in[5];
    float* out = (float*)d_out;

    const int smem = (USIZE + TSIZE) * sizeof(float2);   // 73984 bytes
    cudaFuncSetAttribute(fwd_fft_kernel, cudaFuncAttributeMaxDynamicSharedMemorySize, smem);
    cudaFuncSetAttribute(inv_fft_kernel, cudaFuncAttributeMaxDynamicSharedMemorySize, smem);

    transpose_in_kernel<<<dim3(NGRID / 64, BB), 256>>>(x);
    fwd_fft_kernel<<<BB * CIN, 512, smem>>>();
    specmul_kernel<<<MODES, 256>>>(wr, wi, te, drw, diw);
    inv_fft_kernel<<<BB * COUT, 512, smem>>>();
    transpose_out_kernel<<<dim3(NGRID / 64, BB), 256>>>(out);
}